// round 11
// baseline (speedup 1.0000x reference)
#include <cuda_runtime.h>
#include <cuda_bf16.h>
#include <cstdint>

// ---------------------------------------------------------------------------
// ShiftedWindowAttention — round 11: round-10 pipeline with ALIGNED strides.
//  - GEMM: 4-stage cp.async pipeline, K16 chunks, B_STR=40 (80B, 16B-aligned,
//    conflict-free ldsm), 2 CTAs/SM, 32x32 warp tile.
//  - Attention: round-9 proven layout (QSTR=40) + compile-time source select.
// ---------------------------------------------------------------------------

#define NWIN   2048
#define NTOK   131072
#define HEADS  8
#define HD     32
#define WS2    64
#define DIM    256
#define ATT_SCALE 0.17677669529663687f

// ---------------- scratch ---------------------------------------------------
__device__ __nv_bfloat16 g_wqh[768 * DIM];
__device__ __nv_bfloat16 g_wql[768 * DIM];
__device__ __nv_bfloat16 g_woh[DIM * DIM];
__device__ __nv_bfloat16 g_wol[DIM * DIM];
__device__ __nv_bfloat16 g_qh[NWIN * HEADS * WS2 * HD];
__device__ __nv_bfloat16 g_ql[NWIN * HEADS * WS2 * HD];
__device__ __nv_bfloat16 g_kh[NWIN * HEADS * WS2 * HD];
__device__ __nv_bfloat16 g_kl[NWIN * HEADS * WS2 * HD];
__device__ __nv_bfloat16 g_vh[NWIN * HEADS * WS2 * HD];
__device__ __nv_bfloat16 g_vl[NWIN * HEADS * WS2 * HD];
__device__ __nv_bfloat16 g_ath[NTOK * DIM];
__device__ __nv_bfloat16 g_atl[NTOK * DIM];

// ---------------- helpers ---------------------------------------------------
__device__ __forceinline__ uint32_t smem_u32(const void* p) {
    uint32_t a;
    asm("{ .reg .u64 t; cvta.to.shared.u64 t, %1; cvt.u32.u64 %0, t; }"
        : "=r"(a) : "l"(p));
    return a;
}
__device__ __forceinline__ void ldsm4(uint32_t& r0, uint32_t& r1,
                                      uint32_t& r2, uint32_t& r3, uint32_t a) {
    asm volatile("ldmatrix.sync.aligned.m8n8.x4.shared.b16 {%0,%1,%2,%3}, [%4];"
                 : "=r"(r0), "=r"(r1), "=r"(r2), "=r"(r3) : "r"(a));
}
__device__ __forceinline__ void ldsm4t(uint32_t& r0, uint32_t& r1,
                                       uint32_t& r2, uint32_t& r3, uint32_t a) {
    asm volatile("ldmatrix.sync.aligned.m8n8.x4.trans.shared.b16 {%0,%1,%2,%3}, [%4];"
                 : "=r"(r0), "=r"(r1), "=r"(r2), "=r"(r3) : "r"(a));
}
#define MMA16816(c, a, b)                                                  \
    asm volatile("mma.sync.aligned.m16n8k16.row.col.f32.bf16.bf16.f32 "    \
        "{%0,%1,%2,%3}, {%4,%5,%6,%7}, {%8,%9}, {%0,%1,%2,%3};"            \
        : "+f"((c)[0]), "+f"((c)[1]), "+f"((c)[2]), "+f"((c)[3])           \
        : "r"((a)[0]), "r"((a)[1]), "r"((a)[2]), "r"((a)[3]),              \
          "r"((b)[0]), "r"((b)[1]))

#define CP_ASYNC16(dst, src) \
    asm volatile("cp.async.cg.shared.global [%0], [%1], 16;" \
                 :: "r"(dst), "l"(src) : "memory")
#define CP_COMMIT() asm volatile("cp.async.commit_group;" ::: "memory")
#define CP_WAIT(n)  asm volatile("cp.async.wait_group %0;" :: "n"(n) : "memory")

__device__ __forceinline__ void split2(float x, float y,
                                       uint32_t& hi, uint32_t& lo) {
    __nv_bfloat16 xh = __float2bfloat16_rn(x);
    __nv_bfloat16 yh = __float2bfloat16_rn(y);
    __nv_bfloat16 xl = __float2bfloat16_rn(x - __bfloat162float(xh));
    __nv_bfloat16 yl = __float2bfloat16_rn(y - __bfloat162float(yh));
    __nv_bfloat162 h2 = __halves2bfloat162(xh, yh);
    __nv_bfloat162 l2 = __halves2bfloat162(xl, yl);
    hi = *(uint32_t*)&h2;
    lo = *(uint32_t*)&l2;
}

// ---------------- index map (roll -4,-4 + window split) --------------------
__device__ __forceinline__ int src_offset(int R) {
    int w = R >> 6, t = R & 63;
    int b = w >> 6, widx = w & 63;
    int wy = widx >> 3, wx = widx & 7;
    int ty = t >> 3, tx = t & 7;
    int ys = ((wy << 3) + ty + 4) & 63;
    int xs = ((wx << 3) + tx + 4) & 63;
    return ((b << 12) + (ys << 6) + xs) * DIM;
}

// ---------------- fp32 -> bf16 hi/lo split (weights only) ------------------
__global__ __launch_bounds__(256) void conv_split(
    const float* __restrict__ src, __nv_bfloat16* __restrict__ hp,
    __nv_bfloat16* __restrict__ lp, int n4)
{
    int i = blockIdx.x * 256 + threadIdx.x;
    if (i >= n4) return;
    float4 v = ((const float4*)src)[i];
    uint32_t h0, l0, h1, l1;
    split2(v.x, v.y, h0, l0);
    split2(v.z, v.w, h1, l1);
    ((uint32_t*)hp)[2 * i + 0] = h0;
    ((uint32_t*)hp)[2 * i + 1] = h1;
    ((uint32_t*)lp)[2 * i + 0] = l0;
    ((uint32_t*)lp)[2 * i + 1] = l1;
}

// ---------------------------------------------------------------------------
// HMMA GEMM, M-tile 64 (2 CTAs/SM), warp tile 32x32, K16 chunks,
// 4-stage cp.async pipeline (wait_group 2 => ~2 chunks latency slack),
// one __syncthreads per chunk. B buffer row: [16 hi | 16 lo | 8 pad] bf16.
// ---------------------------------------------------------------------------
#define A_STR   264
#define B_STR   40
#define A_OFF   1024
#define A_SPL   33792                      // 64*264*2
#define B_OFF   (A_OFF + 2 * A_SPL)        // 68608
#define B_BUF   10240                      // 128*40*2
#define SMEM_SZ (B_OFF + 4 * B_BUF)        // 109568

template <int MODE>
__global__ __launch_bounds__(256, 2) void gemm_tc(
    const float* __restrict__ Af,
    const __nv_bfloat16* __restrict__ Ah, const __nv_bfloat16* __restrict__ Al,
    const __nv_bfloat16* __restrict__ Bh, const __nv_bfloat16* __restrict__ Bl,
    const float* __restrict__ bias, float* __restrict__ outp)
{
    constexpr int NTILES = (MODE == 0) ? 6 : 2;
    constexpr int TOTCH  = NTILES * 16;    // K16 chunks
    extern __shared__ char smem[];
    const uint32_t sbase = smem_u32(smem);
    const int tid  = threadIdx.x;
    const int wid  = tid >> 5;
    const int lane = tid & 31;
    const int bx   = blockIdx.x;
    const int m0 = (wid & 1) * 32;          // 2 M-warps
    const int n0 = (wid >> 1) * 32;         // 4 N-warps

    int* rowOff = (int*)smem;
    if (tid < 64) {
        int R = bx * 64 + tid;
        rowOff[tid] = (MODE == 0) ? src_offset(R) : R * DIM;
    }
    __syncthreads();

    // ---- A tile into SMEM (hi/lo, full K) ----
    if (MODE == 0) {
#pragma unroll
        for (int i = 0; i < 16; i++) {
            int idx = tid + i * 256;          // 4096 float4
            int u = idx & 63;
            int r = idx >> 6;
            float4 v = *(const float4*)(Af + rowOff[r] + u * 4);
            uint32_t h0, l0, h1, l1;
            split2(v.x, v.y, h0, l0);
            split2(v.z, v.w, h1, l1);
            char* base = smem + A_OFF + (r * A_STR + u * 4) * 2;
            *(uint2*)base = make_uint2(h0, h1);
            *(uint2*)(base + A_SPL) = make_uint2(l0, l1);
        }
    } else {
#pragma unroll
        for (int i = 0; i < 16; i++) {
            int idx = tid + i * 256;          // 4096 uint4
            int u  = idx & 31;
            int r  = (idx >> 5) & 63;
            int hl = idx >> 11;
            const __nv_bfloat16* s = (hl ? Al : Ah) + rowOff[r] + u * 8;
            uint4 v = *(const uint4*)s;
            *(uint4*)(smem + A_OFF + hl * A_SPL + (r * A_STR + u * 8) * 2) = v;
        }
    }

    // ---- B chunk loader (K16) via cp.async: chunk gg -> buffer b ----
    auto loadB = [&](int gg, int b) {
        const int nb = (gg >> 4) * 128;
        const int kk = (gg & 15) * 16;
#pragma unroll
        for (int i = 0; i < 2; i++) {
            int idx = tid + i * 256;          // 512 x 16B
            int r = idx >> 2, t = idx & 3, hl = t >> 1, u = t & 1;
            const __nv_bfloat16* s = (hl ? Bl : Bh) + (nb + r) * DIM + kk + u * 8;
            uint32_t d = sbase + B_OFF + b * B_BUF +
                         (r * B_STR + hl * 16 + u * 8) * 2;
            CP_ASYNC16(d, s);
        }
        CP_COMMIT();
    };

    loadB(0, 0);
    loadB(1, 1);
    loadB(2, 2);
    CP_WAIT(2);
    __syncthreads();

    const int a_row = lane & 15;
    const int a_col = (lane >> 4) * 8;
    const int b_row = (lane & 7) + ((lane >> 4) << 3);
    const int b_col = ((lane >> 3) & 1) * 8;
    const uint32_t aAddrH = sbase + A_OFF + ((m0 + a_row) * A_STR + a_col) * 2;
    const uint32_t aAddrL = aAddrH + A_SPL;

    float acc[2][4][4];
#pragma unroll
    for (int mf = 0; mf < 2; mf++)
#pragma unroll
        for (int nf = 0; nf < 4; nf++)
#pragma unroll
            for (int q = 0; q < 4; q++) acc[mf][nf][q] = 0.f;

#pragma unroll 1
    for (int g = 0; g < TOTCH; g++) {
        const int c  = g & 15;
        const int nt = g >> 4;

        if (g + 3 < TOTCH) loadB(g + 3, (g + 3) & 3);

        // ---- compute chunk g (K16) ----
        const uint32_t bBase = sbase + B_OFF + (g & 3) * B_BUF;
        const int kk = c * 16;
        uint32_t ah[2][4], al[2][4], bh[4][2], bl[4][2];
#pragma unroll
        for (int mf = 0; mf < 2; mf++) {
            ldsm4(ah[mf][0], ah[mf][1], ah[mf][2], ah[mf][3],
                  aAddrH + (mf * 16 * A_STR + kk) * 2);
            ldsm4(al[mf][0], al[mf][1], al[mf][2], al[mf][3],
                  aAddrL + (mf * 16 * A_STR + kk) * 2);
        }
#pragma unroll
        for (int nf2 = 0; nf2 < 2; nf2++) {
            uint32_t ba = bBase + ((n0 + nf2 * 16 + b_row) * B_STR + b_col) * 2;
            ldsm4(bh[2 * nf2][0], bh[2 * nf2][1],
                  bh[2 * nf2 + 1][0], bh[2 * nf2 + 1][1], ba);
            ldsm4(bl[2 * nf2][0], bl[2 * nf2][1],
                  bl[2 * nf2 + 1][0], bl[2 * nf2 + 1][1], ba + 32);
        }
#pragma unroll
        for (int mf = 0; mf < 2; mf++)
#pragma unroll
            for (int nf = 0; nf < 4; nf++)
                MMA16816(acc[mf][nf], ah[mf], bh[nf]);
#pragma unroll
        for (int mf = 0; mf < 2; mf++)
#pragma unroll
            for (int nf = 0; nf < 4; nf++)
                MMA16816(acc[mf][nf], ah[mf], bl[nf]);
#pragma unroll
        for (int mf = 0; mf < 2; mf++)
#pragma unroll
            for (int nf = 0; nf < 4; nf++)
                MMA16816(acc[mf][nf], al[mf], bh[nf]);

        // ---- epilogue at end of each n-tile ----
        if (c == 15) {
            const int erow = lane >> 2;
            const int ecol = (lane & 3) * 2;
            if (MODE == 0) {
                const int bsel = (nt * 128 + n0) >> 8;   // uniform per warp
                __nv_bfloat16* dh = (bsel == 0) ? g_qh : (bsel == 1) ? g_kh : g_vh;
                __nv_bfloat16* dl = (bsel == 0) ? g_ql : (bsel == 1) ? g_kl : g_vl;
#pragma unroll
                for (int mf = 0; mf < 2; mf++) {
                    int R0 = bx * 64 + m0 + mf * 16 + erow;
                    int w0 = R0 >> 6, t0 = R0 & 63;
                    int R1 = R0 + 8;
                    int w1 = R1 >> 6, t1 = R1 & 63;
#pragma unroll
                    for (int nf = 0; nf < 4; nf++) {
                        int jg = nt * 128 + n0 + nf * 8 + ecol;
                        float bx0 = __ldg(&bias[jg]);
                        float bx1 = __ldg(&bias[jg + 1]);
                        int rem = jg & 255;
                        int h = rem >> 5, d = rem & 31;
                        uint32_t hi, lo;
                        int off0 = (((w0 << 3) + h) * WS2 + t0) * HD + d;
                        split2(acc[mf][nf][0] + bx0, acc[mf][nf][1] + bx1, hi, lo);
                        *(uint32_t*)&dh[off0] = hi;
                        *(uint32_t*)&dl[off0] = lo;
                        int off1 = (((w1 << 3) + h) * WS2 + t1) * HD + d;
                        split2(acc[mf][nf][2] + bx0, acc[mf][nf][3] + bx1, hi, lo);
                        *(uint32_t*)&dh[off1] = hi;
                        *(uint32_t*)&dl[off1] = lo;
                    }
                }
            } else {
#pragma unroll
                for (int mf = 0; mf < 2; mf++) {
                    int R0 = bx * 64 + m0 + mf * 16 + erow;
                    int so0 = src_offset(R0);
                    int so1 = src_offset(R0 + 8);
#pragma unroll
                    for (int nf = 0; nf < 4; nf++) {
                        int jg = nt * 128 + n0 + nf * 8 + ecol;
                        float bx0 = __ldg(&bias[jg]);
                        float bx1 = __ldg(&bias[jg + 1]);
                        *(float2*)&outp[so0 + jg] =
                            make_float2(acc[mf][nf][0] + bx0, acc[mf][nf][1] + bx1);
                        *(float2*)&outp[so1 + jg] =
                            make_float2(acc[mf][nf][2] + bx0, acc[mf][nf][3] + bx1);
                    }
                }
            }
#pragma unroll
            for (int mf = 0; mf < 2; mf++)
#pragma unroll
                for (int nf = 0; nf < 4; nf++)
#pragma unroll
                    for (int q = 0; q < 4; q++) acc[mf][nf][q] = 0.f;
        }

        CP_WAIT(2);
        __syncthreads();
    }
}

// ---------------------------------------------------------------------------
// HMMA attention — round-9 proven layout (QSTR=40), compile-time source
// selection in the loader (no local-memory pointer array).
// ---------------------------------------------------------------------------
#define QSTR 40
#define T_SZ 10240                   // 2 heads * 64 rows * QSTR * 2B
#define AQH 0
#define AQL (1 * T_SZ)
#define AKH (2 * T_SZ)
#define AKL (3 * T_SZ)
#define AVH (4 * T_SZ)
#define AVL (5 * T_SZ)
#define APS (6 * T_SZ)
#define ARG (APS + 1800)
#define ATT_SMEM (ARG + 256)

__global__ __launch_bounds__(128) void attn_mma(const float* __restrict__ pos_enc)
{
    extern __shared__ char smem[];
    const uint32_t sbase = smem_u32(smem);
    const int w    = blockIdx.x;
    const int hp   = blockIdx.y;
    const int tid  = threadIdx.x;
    const int wid  = tid >> 5;
    const int lane = tid & 31;
    const int hl2  = wid >> 1;
    const int m0   = (wid & 1) * 32;

    {
        const int whbase = ((w << 3) + (hp << 1)) * WS2 * HD;
#pragma unroll
        for (int tz = 0; tz < 6; tz++) {
            const __nv_bfloat16* base =
                (tz == 0) ? g_qh : (tz == 1) ? g_ql :
                (tz == 2) ? g_kh : (tz == 3) ? g_kl :
                (tz == 4) ? g_vh : g_vl;
#pragma unroll
            for (int j = 0; j < 4; j++) {
                int idx = tid + j * 128;       // 0..511
                int u = idx & 3, r = (idx >> 2) & 63, hh = idx >> 8;
                uint4 v = *(const uint4*)(base + whbase +
                                          (hh * WS2 + r) * HD + u * 8);
                *(uint4*)(smem + tz * T_SZ + ((hh * 64 + r) * QSTR + u * 8) * 2) = v;
            }
        }
        float* psf = (float*)(smem + APS);
        for (int i = tid; i < 450; i += 128)
            psf[i] = pos_enc[(hp * 2) * 225 + i];
        int* rgp = (int*)(smem + ARG);
        if (tid < 64) {
            int widx = w & 63;
            int wy = widx >> 3, wx = widx & 7;
            int ry = (wy < 7) ? 0 : ((tid >> 3) < 4 ? 1 : 2);
            int rx = (wx < 7) ? 0 : ((tid & 7) < 4 ? 1 : 2);
            rgp[tid] = ry * 3 + rx;
        }
    }
    __syncthreads();

    const float* ps = (const float*)(smem + APS) + hl2 * 225;
    const int* rg = (const int*)(smem + ARG);

    float s[2][8][4];
#pragma unroll
    for (int mf = 0; mf < 2; mf++)
#pragma unroll
        for (int nf = 0; nf < 8; nf++)
#pragma unroll
            for (int q = 0; q < 4; q++) s[mf][nf][q] = 0.f;

    const int a_row = lane & 15;
    const int a_col = (lane >> 4) * 8;
    const int b_row = (lane & 7) + ((lane >> 4) << 3);
    const int b_col = ((lane >> 3) & 1) * 8;
    const uint32_t qA = sbase + AQH + ((hl2 * 64 + m0 + a_row) * QSTR + a_col) * 2;
    const uint32_t kB = sbase + AKH + ((hl2 * 64 + b_row) * QSTR + b_col) * 2;

#pragma unroll
    for (int ks = 0; ks < 2; ks++) {
        uint32_t ah[2][4], al[2][4], bh[8][2], bl[8][2];
#pragma unroll
        for (int mf = 0; mf < 2; mf++) {
            uint32_t a = qA + (mf * 16 * QSTR + ks * 16) * 2;
            ldsm4(ah[mf][0], ah[mf][1], ah[mf][2], ah[mf][3], a);
            ldsm4(al[mf][0], al[mf][1], al[mf][2], al[mf][3], a + T_SZ);
        }
#pragma unroll
        for (int nf2 = 0; nf2 < 4; nf2++) {
            uint32_t b = kB + (nf2 * 16 * QSTR + ks * 16) * 2;
            ldsm4(bh[2 * nf2][0], bh[2 * nf2][1],
                  bh[2 * nf2 + 1][0], bh[2 * nf2 + 1][1], b);
            ldsm4(bl[2 * nf2][0], bl[2 * nf2][1],
                  bl[2 * nf2 + 1][0], bl[2 * nf2 + 1][1], b + T_SZ);
        }
#pragma unroll
        for (int mf = 0; mf < 2; mf++)
#pragma unroll
            for (int nf = 0; nf < 8; nf++) {
                MMA16816(s[mf][nf], ah[mf], bh[nf]);
                MMA16816(s[mf][nf], ah[mf], bl[nf]);
                MMA16816(s[mf][nf], al[mf], bh[nf]);
            }
    }

    const int rowl = lane >> 2;
    const int colb = (lane & 3) * 2;
#pragma unroll
    for (int mf = 0; mf < 2; mf++) {
        int t1a = m0 + mf * 16 + rowl, t1b = t1a + 8;
        int y1a = t1a >> 3, x1a = t1a & 7;
        int y1b = t1b >> 3, x1b = t1b & 7;
        int rga = rg[t1a], rgb = rg[t1b];
        float mxa = -1e30f, mxb = -1e30f;
#pragma unroll
        for (int nf = 0; nf < 8; nf++)
#pragma unroll
            for (int e = 0; e < 2; e++) {
                int t2 = nf * 8 + colb + e;
                int y2 = t2 >> 3, x2 = t2 & 7;
                int rgc = rg[t2];
                float va = fmaf(s[mf][nf][e], ATT_SCALE,
                                ps[(y1a - y2 + 7) * 15 + (x1a - x2 + 7)]);
                float vb = fmaf(s[mf][nf][2 + e], ATT_SCALE,
                                ps[(y1b - y2 + 7) * 15 + (x1b - x2 + 7)]);
                if (rgc != rga) va = -1e30f;
                if (rgc != rgb) vb = -1e30f;
                s[mf][nf][e] = va;
                s[mf][nf][2 + e] = vb;
                mxa = fmaxf(mxa, va);
                mxb = fmaxf(mxb, vb);
            }
        mxa = fmaxf(mxa, __shfl_xor_sync(0xffffffffu, mxa, 1));
        mxa = fmaxf(mxa, __shfl_xor_sync(0xffffffffu, mxa, 2));
        mxb = fmaxf(mxb, __shfl_xor_sync(0xffffffffu, mxb, 1));
        mxb = fmaxf(mxb, __shfl_xor_sync(0xffffffffu, mxb, 2));
        float sma = 0.f, smb = 0.f;
#pragma unroll
        for (int nf = 0; nf < 8; nf++)
#pragma unroll
            for (int e = 0; e < 2; e++) {
                float ea = __expf(s[mf][nf][e] - mxa);
                float eb = __expf(s[mf][nf][2 + e] - mxb);
                s[mf][nf][e] = ea;
                s[mf][nf][2 + e] = eb;
                sma += ea;
                smb += eb;
            }
        sma += __shfl_xor_sync(0xffffffffu, sma, 1);
        sma += __shfl_xor_sync(0xffffffffu, sma, 2);
        smb += __shfl_xor_sync(0xffffffffu, smb, 1);
        smb += __shfl_xor_sync(0xffffffffu, smb, 2);
        float ia = 1.0f / sma, ib = 1.0f / smb;
#pragma unroll
        for (int nf = 0; nf < 8; nf++) {
            s[mf][nf][0] *= ia; s[mf][nf][1] *= ia;
            s[mf][nf][2] *= ib; s[mf][nf][3] *= ib;
        }
    }

    float o[2][4][4];
#pragma unroll
    for (int mf = 0; mf < 2; mf++)
#pragma unroll
        for (int nf = 0; nf < 4; nf++)
#pragma unroll
            for (int q = 0; q < 4; q++) o[mf][nf][q] = 0.f;

    const int v_row = (lane & 7) + ((lane >> 3) & 1) * 8;
    const int v_col = (lane >> 4) * 8;
#pragma unroll
    for (int kf = 0; kf < 4; kf++) {
        uint32_t aH[2][4], aL[2][4];
#pragma unroll
        for (int mf = 0; mf < 2; mf++) {
            split2(s[mf][2 * kf][0],     s[mf][2 * kf][1],     aH[mf][0], aL[mf][0]);
            split2(s[mf][2 * kf][2],     s[mf][2 * kf][3],     aH[mf][1], aL[mf][1]);
            split2(s[mf][2 * kf + 1][0], s[mf][2 * kf + 1][1], aH[mf][2], aL[mf][2]);
            split2(s[mf][2 * kf + 1][2], s[mf][2 * kf + 1][3], aH[mf][3], aL[mf][3]);
        }
        uint32_t bH[4][2], bL[4][2];
#pragma unroll
        for (int dh = 0; dh < 2; dh++) {
            uint32_t a = sbase + AVH +
                ((hl2 * 64 + kf * 16 + v_row) * QSTR + dh * 16 + v_col) * 2;
            ldsm4t(bH[2 * dh][0], bH[2 * dh][1],
                   bH[2 * dh + 1][0], bH[2 * dh + 1][1], a);
            ldsm4t(bL[2 * dh][0], bL[2 * dh][1],
                   bL[2 * dh + 1][0], bL[2 * dh + 1][1], a + T_SZ);
        }
#pragma unroll
        for (int mf = 0; mf < 2; mf++)
#pragma unroll
            for (int nf = 0; nf < 4; nf++) {
                MMA16816(o[mf][nf], aH[mf], bH[nf]);
                MMA16816(o[mf][nf], aH[mf], bL[nf]);
                MMA16816(o[mf][nf], aL[mf], bH[nf]);
            }
    }

    const int head = hp * 2 + hl2;
#pragma unroll
    for (int mf = 0; mf < 2; mf++) {
        int t1a = m0 + mf * 16 + rowl, t1b = t1a + 8;
#pragma unroll
        for (int nf = 0; nf < 4; nf++) {
            int gcol = head * 32 + nf * 8 + colb;
            uint32_t hi, lo;
            split2(o[mf][nf][0], o[mf][nf][1], hi, lo);
            *(uint32_t*)&g_ath[(w * WS2 + t1a) * DIM + gcol] = hi;
            *(uint32_t*)&g_atl[(w * WS2 + t1a) * DIM + gcol] = lo;
            split2(o[mf][nf][2], o[mf][nf][3], hi, lo);
            *(uint32_t*)&g_ath[(w * WS2 + t1b) * DIM + gcol] = hi;
            *(uint32_t*)&g_atl[(w * WS2 + t1b) * DIM + gcol] = lo;
        }
    }
}

// ---------------------------------------------------------------------------
extern "C" void kernel_launch(void* const* d_in, const int* in_sizes, int n_in,
                              void* d_out, int out_size)
{
    const float* x       = (const float*)d_in[0];
    const float* w_qkv   = (const float*)d_in[1];
    const float* b_qkv   = (const float*)d_in[2];
    const float* w_out   = (const float*)d_in[3];
    const float* b_out   = (const float*)d_in[4];
    const float* pos_enc = (const float*)d_in[5];
    float* out = (float*)d_out;

    cudaFuncSetAttribute(gemm_tc<0>, cudaFuncAttributeMaxDynamicSharedMemorySize, SMEM_SZ);
    cudaFuncSetAttribute(gemm_tc<1>, cudaFuncAttributeMaxDynamicSharedMemorySize, SMEM_SZ);
    cudaFuncSetAttribute(attn_mma, cudaFuncAttributeMaxDynamicSharedMemorySize, ATT_SMEM);

    __nv_bfloat16 *wqh, *wql, *woh, *wol, *ath, *atl;
    cudaGetSymbolAddress((void**)&wqh, g_wqh);
    cudaGetSymbolAddress((void**)&wql, g_wql);
    cudaGetSymbolAddress((void**)&woh, g_woh);
    cudaGetSymbolAddress((void**)&wol, g_wol);
    cudaGetSymbolAddress((void**)&ath, g_ath);
    cudaGetSymbolAddress((void**)&atl, g_atl);

    conv_split<<<(768 * DIM / 4 + 255) / 256, 256>>>(w_qkv, wqh, wql, 768 * DIM / 4);
    conv_split<<<(DIM * DIM / 4 + 255) / 256, 256>>>(w_out, woh, wol, DIM * DIM / 4);

    gemm_tc<0><<<NTOK / 64, 256, SMEM_SZ>>>(x, nullptr, nullptr, wqh, wql, b_qkv, nullptr);
    attn_mma<<<dim3(NWIN, 4), 128, ATT_SMEM>>>(pos_enc);
    gemm_tc<1><<<NTOK / 64, 256, SMEM_SZ>>>(nullptr, ath, atl, woh, wol, b_out, out);
}

// round 12
// speedup vs baseline: 1.5065x; 1.5065x over previous
#include <cuda_runtime.h>
#include <cuda_fp16.h>
#include <cstdint>

// ---------------------------------------------------------------------------
// ShiftedWindowAttention — round 12: single-pass fp16 HMMA everywhere.
// fp16 eps=2^-11 -> predicted rel_err ~1.5e-4 (<1e-3 gate, 6.7x margin),
// based on measured 4.77e-6 at effective eps 1.5e-5 (linear noise model).
// MMA count /3, ldsm /2, smem /2 vs split-bf16: GEMM 3 CTAs/SM, attn 4 CTAs/SM.
// ---------------------------------------------------------------------------

#define NWIN   2048
#define NTOK   131072
#define HEADS  8
#define HD     32
#define WS2    64
#define DIM    256
#define ATT_SCALE 0.17677669529663687f

// ---------------- scratch ---------------------------------------------------
__device__ __half g_wq16[768 * DIM];
__device__ __half g_wo16[DIM * DIM];
__device__ __half g_q16[NWIN * HEADS * WS2 * HD];
__device__ __half g_k16[NWIN * HEADS * WS2 * HD];
__device__ __half g_v16[NWIN * HEADS * WS2 * HD];
__device__ __half g_at16[NTOK * DIM];

// ---------------- helpers ---------------------------------------------------
__device__ __forceinline__ uint32_t smem_u32(const void* p) {
    uint32_t a;
    asm("{ .reg .u64 t; cvta.to.shared.u64 t, %1; cvt.u32.u64 %0, t; }"
        : "=r"(a) : "l"(p));
    return a;
}
__device__ __forceinline__ void ldsm4(uint32_t& r0, uint32_t& r1,
                                      uint32_t& r2, uint32_t& r3, uint32_t a) {
    asm volatile("ldmatrix.sync.aligned.m8n8.x4.shared.b16 {%0,%1,%2,%3}, [%4];"
                 : "=r"(r0), "=r"(r1), "=r"(r2), "=r"(r3) : "r"(a));
}
__device__ __forceinline__ void ldsm4t(uint32_t& r0, uint32_t& r1,
                                       uint32_t& r2, uint32_t& r3, uint32_t a) {
    asm volatile("ldmatrix.sync.aligned.m8n8.x4.trans.shared.b16 {%0,%1,%2,%3}, [%4];"
                 : "=r"(r0), "=r"(r1), "=r"(r2), "=r"(r3) : "r"(a));
}
#define MMA16816(c, a, b)                                                  \
    asm volatile("mma.sync.aligned.m16n8k16.row.col.f32.f16.f16.f32 "      \
        "{%0,%1,%2,%3}, {%4,%5,%6,%7}, {%8,%9}, {%0,%1,%2,%3};"            \
        : "+f"((c)[0]), "+f"((c)[1]), "+f"((c)[2]), "+f"((c)[3])           \
        : "r"((a)[0]), "r"((a)[1]), "r"((a)[2]), "r"((a)[3]),              \
          "r"((b)[0]), "r"((b)[1]))

#define CP_ASYNC16(dst, src) \
    asm volatile("cp.async.cg.shared.global [%0], [%1], 16;" \
                 :: "r"(dst), "l"(src) : "memory")
#define CP_COMMIT() asm volatile("cp.async.commit_group;" ::: "memory")
#define CP_WAIT0()  asm volatile("cp.async.wait_group 0;" ::: "memory")

__device__ __forceinline__ uint32_t packh2(float x, float y) {
    __half2 h = __floats2half2_rn(x, y);
    return *(uint32_t*)&h;
}

// ---------------- index map (roll -4,-4 + window split) --------------------
__device__ __forceinline__ int src_offset(int R) {
    int w = R >> 6, t = R & 63;
    int b = w >> 6, widx = w & 63;
    int wy = widx >> 3, wx = widx & 7;
    int ty = t >> 3, tx = t & 7;
    int ys = ((wy << 3) + ty + 4) & 63;
    int xs = ((wx << 3) + tx + 4) & 63;
    return ((b << 12) + (ys << 6) + xs) * DIM;
}

// ---------------- fp32 -> fp16 convert (weights only) ----------------------
__global__ __launch_bounds__(256) void conv16(
    const float* __restrict__ src, __half* __restrict__ dst, int n4)
{
    int i = blockIdx.x * 256 + threadIdx.x;
    if (i >= n4) return;
    float4 v = ((const float4*)src)[i];
    ((uint32_t*)dst)[2 * i + 0] = packh2(v.x, v.y);
    ((uint32_t*)dst)[2 * i + 1] = packh2(v.z, v.w);
}

// ---------------------------------------------------------------------------
// fp16 HMMA GEMM. M-tile 64, warp tile 32x32 (8 warps: 2M x 4N over 64x128),
// K32 chunks, 2-buffer cp.async, one __syncthreads per chunk. 3 CTAs/SM.
// MODE 0: qkv — A = fp32 x gathered + converted on the fly; epilogue writes
//         fp16 q/k/v in [win][head][t][d].
// MODE 1: out-proj — A = g_at16; epilogue scatters fp32 via src_offset.
// ---------------------------------------------------------------------------
#define A_STR   264
#define B_STR   40
#define A_OFF   1024
#define A_SZ    33792                      // 64*264*2
#define B_OFF   (A_OFF + A_SZ)             // 34816
#define B_BUF   10240                      // 128*40*2
#define SMEM_SZ (B_OFF + 2 * B_BUF)        // 55296

template <int MODE>
__global__ __launch_bounds__(256, 3) void gemm_tc(
    const float* __restrict__ Af,
    const __half* __restrict__ A16,
    const __half* __restrict__ B16,
    const float* __restrict__ bias, float* __restrict__ outp)
{
    constexpr int NTILES = (MODE == 0) ? 6 : 2;
    constexpr int TOTCH  = NTILES * 8;     // K32 chunks
    extern __shared__ char smem[];
    const uint32_t sbase = smem_u32(smem);
    const int tid  = threadIdx.x;
    const int wid  = tid >> 5;
    const int lane = tid & 31;
    const int bx   = blockIdx.x;
    const int m0 = (wid & 1) * 32;          // 2 M-warps
    const int n0 = (wid >> 1) * 32;         // 4 N-warps

    int* rowOff = (int*)smem;
    if (tid < 64) {
        int R = bx * 64 + tid;
        rowOff[tid] = (MODE == 0) ? src_offset(R) : R * DIM;
    }
    __syncthreads();

    // ---- A tile into SMEM (fp16, full K, stride 264) ----
    if (MODE == 0) {
#pragma unroll
        for (int i = 0; i < 16; i++) {
            int idx = tid + i * 256;          // 4096 float4
            int u = idx & 63;                 // float4 within row
            int r = idx >> 6;
            float4 v = *(const float4*)(Af + rowOff[r] + u * 4);
            uint2 p = make_uint2(packh2(v.x, v.y), packh2(v.z, v.w));
            *(uint2*)(smem + A_OFF + (r * A_STR + u * 4) * 2) = p;
        }
    } else {
#pragma unroll
        for (int i = 0; i < 8; i++) {
            int idx = tid + i * 256;          // 2048 uint4
            int u = idx & 31;
            int r = idx >> 5;
            uint4 v = *(const uint4*)(A16 + rowOff[r] + u * 8);
            *(uint4*)(smem + A_OFF + (r * A_STR + u * 8) * 2) = v;
        }
    }

    // ---- B chunk loader via cp.async: chunk gg -> buffer b ----
    auto loadB = [&](int gg, int b) {
        const int nb = (gg >> 3) * 128;
        const int kk = (gg & 7) * 32;
#pragma unroll
        for (int i = 0; i < 2; i++) {
            int idx = tid + i * 256;          // 512 x 16B
            int r = idx >> 2, u = idx & 3;
            const __half* s = B16 + (nb + r) * DIM + kk + u * 8;
            uint32_t d = sbase + B_OFF + b * B_BUF + (r * B_STR + u * 8) * 2;
            CP_ASYNC16(d, s);
        }
        CP_COMMIT();
    };

    loadB(0, 0);
    CP_WAIT0();
    __syncthreads();

    const int a_row = lane & 15;
    const int a_col = (lane >> 4) * 8;
    const int b_row = (lane & 7) + ((lane >> 4) << 3);
    const int b_col = ((lane >> 3) & 1) * 8;
    const uint32_t aAddr = sbase + A_OFF + ((m0 + a_row) * A_STR + a_col) * 2;

    float acc[2][4][4];
#pragma unroll
    for (int mf = 0; mf < 2; mf++)
#pragma unroll
        for (int nf = 0; nf < 4; nf++)
#pragma unroll
            for (int q = 0; q < 4; q++) acc[mf][nf][q] = 0.f;

#pragma unroll 1
    for (int g = 0; g < TOTCH; g++) {
        const int c  = g & 7;
        const int nt = g >> 3;

        if (g + 1 < TOTCH) loadB(g + 1, (g + 1) & 1);

        // ---- compute chunk g ----
        const uint32_t bBase = sbase + B_OFF + (g & 1) * B_BUF;
#pragma unroll
        for (int ks = 0; ks < 2; ks++) {
            const int kk = c * 32 + ks * 16;
            uint32_t ah[2][4], bh[4][2];
#pragma unroll
            for (int mf = 0; mf < 2; mf++)
                ldsm4(ah[mf][0], ah[mf][1], ah[mf][2], ah[mf][3],
                      aAddr + (mf * 16 * A_STR + kk) * 2);
#pragma unroll
            for (int nf2 = 0; nf2 < 2; nf2++) {
                uint32_t ba = bBase +
                    ((n0 + nf2 * 16 + b_row) * B_STR + ks * 16 + b_col) * 2;
                ldsm4(bh[2 * nf2][0], bh[2 * nf2][1],
                      bh[2 * nf2 + 1][0], bh[2 * nf2 + 1][1], ba);
            }
#pragma unroll
            for (int mf = 0; mf < 2; mf++)
#pragma unroll
                for (int nf = 0; nf < 4; nf++)
                    MMA16816(acc[mf][nf], ah[mf], bh[nf]);
        }

        // ---- epilogue at end of each n-tile ----
        if (c == 7) {
            const int erow = lane >> 2;
            const int ecol = (lane & 3) * 2;
            if (MODE == 0) {
                const int bsel = (nt * 128 + n0) >> 8;   // uniform per warp
                __half* dst = (bsel == 0) ? g_q16 : (bsel == 1) ? g_k16 : g_v16;
#pragma unroll
                for (int mf = 0; mf < 2; mf++) {
                    int R0 = bx * 64 + m0 + mf * 16 + erow;
                    int w0 = R0 >> 6, t0 = R0 & 63;
                    int R1 = R0 + 8;
                    int w1 = R1 >> 6, t1 = R1 & 63;
#pragma unroll
                    for (int nf = 0; nf < 4; nf++) {
                        int jg = nt * 128 + n0 + nf * 8 + ecol;
                        float bx0 = __ldg(&bias[jg]);
                        float bx1 = __ldg(&bias[jg + 1]);
                        int rem = jg & 255;
                        int h = rem >> 5, d = rem & 31;
                        int off0 = (((w0 << 3) + h) * WS2 + t0) * HD + d;
                        *(uint32_t*)&dst[off0] =
                            packh2(acc[mf][nf][0] + bx0, acc[mf][nf][1] + bx1);
                        int off1 = (((w1 << 3) + h) * WS2 + t1) * HD + d;
                        *(uint32_t*)&dst[off1] =
                            packh2(acc[mf][nf][2] + bx0, acc[mf][nf][3] + bx1);
                    }
                }
            } else {
#pragma unroll
                for (int mf = 0; mf < 2; mf++) {
                    int R0 = bx * 64 + m0 + mf * 16 + erow;
                    int so0 = src_offset(R0);
                    int so1 = src_offset(R0 + 8);
#pragma unroll
                    for (int nf = 0; nf < 4; nf++) {
                        int jg = nt * 128 + n0 + nf * 8 + ecol;
                        float bx0 = __ldg(&bias[jg]);
                        float bx1 = __ldg(&bias[jg + 1]);
                        *(float2*)&outp[so0 + jg] =
                            make_float2(acc[mf][nf][0] + bx0, acc[mf][nf][1] + bx1);
                        *(float2*)&outp[so1 + jg] =
                            make_float2(acc[mf][nf][2] + bx0, acc[mf][nf][3] + bx1);
                    }
                }
            }
#pragma unroll
            for (int mf = 0; mf < 2; mf++)
#pragma unroll
                for (int nf = 0; nf < 4; nf++)
#pragma unroll
                    for (int q = 0; q < 4; q++) acc[mf][nf][q] = 0.f;
        }

        CP_WAIT0();
        __syncthreads();
    }
}

// ---------------------------------------------------------------------------
// fp16 HMMA attention. Block = 1 window x 2 heads, 4 warps; 4 CTAs/SM.
// ---------------------------------------------------------------------------
#define QSTR 40
#define T_SZ 10240                   // 2 heads * 64 rows * QSTR * 2B
#define AQ  0
#define AK  (1 * T_SZ)
#define AV  (2 * T_SZ)
#define APS (3 * T_SZ)               // 30720
#define ARG (APS + 1800)
#define ATT_SMEM (ARG + 256)         // 32776

__global__ __launch_bounds__(128, 4) void attn_mma(const float* __restrict__ pos_enc)
{
    extern __shared__ char smem[];
    const uint32_t sbase = smem_u32(smem);
    const int w    = blockIdx.x;
    const int hp   = blockIdx.y;
    const int tid  = threadIdx.x;
    const int wid  = tid >> 5;
    const int lane = tid & 31;
    const int hl2  = wid >> 1;
    const int m0   = (wid & 1) * 32;

    {
        const int whbase = ((w << 3) + (hp << 1)) * WS2 * HD;
#pragma unroll
        for (int tz = 0; tz < 3; tz++) {
            const __half* base = (tz == 0) ? g_q16 : (tz == 1) ? g_k16 : g_v16;
#pragma unroll
            for (int j = 0; j < 4; j++) {
                int idx = tid + j * 128;       // 0..511
                int u = idx & 3, r = (idx >> 2) & 63, hh = idx >> 8;
                uint4 v = *(const uint4*)(base + whbase +
                                          (hh * WS2 + r) * HD + u * 8);
                *(uint4*)(smem + tz * T_SZ + ((hh * 64 + r) * QSTR + u * 8) * 2) = v;
            }
        }
        float* psf = (float*)(smem + APS);
        for (int i = tid; i < 450; i += 128)
            psf[i] = pos_enc[(hp * 2) * 225 + i];
        int* rgp = (int*)(smem + ARG);
        if (tid < 64) {
            int widx = w & 63;
            int wy = widx >> 3, wx = widx & 7;
            int ry = (wy < 7) ? 0 : ((tid >> 3) < 4 ? 1 : 2);
            int rx = (wx < 7) ? 0 : ((tid & 7) < 4 ? 1 : 2);
            rgp[tid] = ry * 3 + rx;
        }
    }
    __syncthreads();

    const float* ps = (const float*)(smem + APS) + hl2 * 225;
    const int* rg = (const int*)(smem + ARG);

    // ---- QK^T ----
    float s[2][8][4];
#pragma unroll
    for (int mf = 0; mf < 2; mf++)
#pragma unroll
        for (int nf = 0; nf < 8; nf++)
#pragma unroll
            for (int q = 0; q < 4; q++) s[mf][nf][q] = 0.f;

    const int a_row = lane & 15;
    const int a_col = (lane >> 4) * 8;
    const int b_row = (lane & 7) + ((lane >> 4) << 3);
    const int b_col = ((lane >> 3) & 1) * 8;
    const uint32_t qA = sbase + AQ + ((hl2 * 64 + m0 + a_row) * QSTR + a_col) * 2;
    const uint32_t kB = sbase + AK + ((hl2 * 64 + b_row) * QSTR + b_col) * 2;

#pragma unroll
    for (int ks = 0; ks < 2; ks++) {
        uint32_t ah[2][4], bh[8][2];
#pragma unroll
        for (int mf = 0; mf < 2; mf++)
            ldsm4(ah[mf][0], ah[mf][1], ah[mf][2], ah[mf][3],
                  qA + (mf * 16 * QSTR + ks * 16) * 2);
#pragma unroll
        for (int nf2 = 0; nf2 < 4; nf2++) {
            uint32_t b = kB + (nf2 * 16 * QSTR + ks * 16) * 2;
            ldsm4(bh[2 * nf2][0], bh[2 * nf2][1],
                  bh[2 * nf2 + 1][0], bh[2 * nf2 + 1][1], b);
        }
#pragma unroll
        for (int mf = 0; mf < 2; mf++)
#pragma unroll
            for (int nf = 0; nf < 8; nf++)
                MMA16816(s[mf][nf], ah[mf], bh[nf]);
    }

    // ---- bias + mask + softmax (fragment registers) ----
    const int rowl = lane >> 2;
    const int colb = (lane & 3) * 2;
#pragma unroll
    for (int mf = 0; mf < 2; mf++) {
        int t1a = m0 + mf * 16 + rowl, t1b = t1a + 8;
        int y1a = t1a >> 3, x1a = t1a & 7;
        int y1b = t1b >> 3, x1b = t1b & 7;
        int rga = rg[t1a], rgb = rg[t1b];
        float mxa = -1e30f, mxb = -1e30f;
#pragma unroll
        for (int nf = 0; nf < 8; nf++)
#pragma unroll
            for (int e = 0; e < 2; e++) {
                int t2 = nf * 8 + colb + e;
                int y2 = t2 >> 3, x2 = t2 & 7;
                int rgc = rg[t2];
                float va = fmaf(s[mf][nf][e], ATT_SCALE,
                                ps[(y1a - y2 + 7) * 15 + (x1a - x2 + 7)]);
                float vb = fmaf(s[mf][nf][2 + e], ATT_SCALE,
                                ps[(y1b - y2 + 7) * 15 + (x1b - x2 + 7)]);
                if (rgc != rga) va = -1e30f;
                if (rgc != rgb) vb = -1e30f;
                s[mf][nf][e] = va;
                s[mf][nf][2 + e] = vb;
                mxa = fmaxf(mxa, va);
                mxb = fmaxf(mxb, vb);
            }
        mxa = fmaxf(mxa, __shfl_xor_sync(0xffffffffu, mxa, 1));
        mxa = fmaxf(mxa, __shfl_xor_sync(0xffffffffu, mxa, 2));
        mxb = fmaxf(mxb, __shfl_xor_sync(0xffffffffu, mxb, 1));
        mxb = fmaxf(mxb, __shfl_xor_sync(0xffffffffu, mxb, 2));
        float sma = 0.f, smb = 0.f;
#pragma unroll
        for (int nf = 0; nf < 8; nf++)
#pragma unroll
            for (int e = 0; e < 2; e++) {
                float ea = __expf(s[mf][nf][e] - mxa);
                float eb = __expf(s[mf][nf][2 + e] - mxb);
                s[mf][nf][e] = ea;
                s[mf][nf][2 + e] = eb;
                sma += ea;
                smb += eb;
            }
        sma += __shfl_xor_sync(0xffffffffu, sma, 1);
        sma += __shfl_xor_sync(0xffffffffu, sma, 2);
        smb += __shfl_xor_sync(0xffffffffu, smb, 1);
        smb += __shfl_xor_sync(0xffffffffu, smb, 2);
        float ia = 1.0f / sma, ib = 1.0f / smb;
#pragma unroll
        for (int nf = 0; nf < 8; nf++) {
            s[mf][nf][0] *= ia; s[mf][nf][1] *= ia;
            s[mf][nf][2] *= ib; s[mf][nf][3] *= ib;
        }
    }

    // ---- PV: P repacked to fp16 A-frags, V via ldmatrix.trans ----
    float o[2][4][4];
#pragma unroll
    for (int mf = 0; mf < 2; mf++)
#pragma unroll
        for (int nf = 0; nf < 4; nf++)
#pragma unroll
            for (int q = 0; q < 4; q++) o[mf][nf][q] = 0.f;

    const int v_row = (lane & 7) + ((lane >> 3) & 1) * 8;
    const int v_col = (lane >> 4) * 8;
#pragma unroll
    for (int kf = 0; kf < 4; kf++) {
        uint32_t aP[2][4];
#pragma unroll
        for (int mf = 0; mf < 2; mf++) {
            aP[mf][0] = packh2(s[mf][2 * kf][0],     s[mf][2 * kf][1]);
            aP[mf][1] = packh2(s[mf][2 * kf][2],     s[mf][2 * kf][3]);
            aP[mf][2] = packh2(s[mf][2 * kf + 1][0], s[mf][2 * kf + 1][1]);
            aP[mf][3] = packh2(s[mf][2 * kf + 1][2], s[mf][2 * kf + 1][3]);
        }
        uint32_t bV[4][2];
#pragma unroll
        for (int dh = 0; dh < 2; dh++) {
            uint32_t a = sbase + AV +
                ((hl2 * 64 + kf * 16 + v_row) * QSTR + dh * 16 + v_col) * 2;
            ldsm4t(bV[2 * dh][0], bV[2 * dh][1],
                   bV[2 * dh + 1][0], bV[2 * dh + 1][1], a);
        }
#pragma unroll
        for (int mf = 0; mf < 2; mf++)
#pragma unroll
            for (int nf = 0; nf < 4; nf++)
                MMA16816(o[mf][nf], aP[mf], bV[nf]);
    }

    // ---- epilogue: fp16 output [token][c] for out-projection ----
    const int head = hp * 2 + hl2;
#pragma unroll
    for (int mf = 0; mf < 2; mf++) {
        int t1a = m0 + mf * 16 + rowl, t1b = t1a + 8;
#pragma unroll
        for (int nf = 0; nf < 4; nf++) {
            int gcol = head * 32 + nf * 8 + colb;
            *(uint32_t*)&g_at16[(w * WS2 + t1a) * DIM + gcol] =
                packh2(o[mf][nf][0], o[mf][nf][1]);
            *(uint32_t*)&g_at16[(w * WS2 + t1b) * DIM + gcol] =
                packh2(o[mf][nf][2], o[mf][nf][3]);
        }
    }
}

// ---------------------------------------------------------------------------
extern "C" void kernel_launch(void* const* d_in, const int* in_sizes, int n_in,
                              void* d_out, int out_size)
{
    const float* x       = (const float*)d_in[0];
    const float* w_qkv   = (const float*)d_in[1];
    const float* b_qkv   = (const float*)d_in[2];
    const float* w_out   = (const float*)d_in[3];
    const float* b_out   = (const float*)d_in[4];
    const float* pos_enc = (const float*)d_in[5];
    float* out = (float*)d_out;

    cudaFuncSetAttribute(gemm_tc<0>, cudaFuncAttributeMaxDynamicSharedMemorySize, SMEM_SZ);
    cudaFuncSetAttribute(gemm_tc<1>, cudaFuncAttributeMaxDynamicSharedMemorySize, SMEM_SZ);
    cudaFuncSetAttribute(attn_mma, cudaFuncAttributeMaxDynamicSharedMemorySize, ATT_SMEM);

    __half *wq16, *wo16, *at16;
    cudaGetSymbolAddress((void**)&wq16, g_wq16);
    cudaGetSymbolAddress((void**)&wo16, g_wo16);
    cudaGetSymbolAddress((void**)&at16, g_at16);

    conv16<<<(768 * DIM / 4 + 255) / 256, 256>>>(w_qkv, wq16, 768 * DIM / 4);
    conv16<<<(DIM * DIM / 4 + 255) / 256, 256>>>(w_out, wo16, DIM * DIM / 4);

    gemm_tc<0><<<NTOK / 64, 256, SMEM_SZ>>>(x, nullptr, wq16, b_qkv, nullptr);
    attn_mma<<<dim3(NWIN, 4), 128, ATT_SMEM>>>(pos_enc);
    gemm_tc<1><<<NTOK / 64, 256, SMEM_SZ>>>(nullptr, at16, wo16, b_out, out);
}

// round 13
// speedup vs baseline: 2.1309x; 1.4145x over previous
#include <cuda_runtime.h>
#include <cuda_fp16.h>
#include <cstdint>

// ---------------------------------------------------------------------------
// ShiftedWindowAttention — round 13: fp16 HMMA.
//  - GEMM: M-tile 128, warp tile 32x64 (32 MMA : 12 ldsm per chunk),
//    K32 chunks, 2-buffer cp.async, 2 CTAs/SM, no spills (fp16 frees regs).
//  - Attention: separable bias index + mask branch only for boundary windows.
// ---------------------------------------------------------------------------

#define NWIN   2048
#define NTOK   131072
#define HEADS  8
#define HD     32
#define WS2    64
#define DIM    256
#define ATT_SCALE 0.17677669529663687f

// ---------------- scratch ---------------------------------------------------
__device__ __half g_wq16[768 * DIM];
__device__ __half g_wo16[DIM * DIM];
__device__ __half g_q16[NWIN * HEADS * WS2 * HD];
__device__ __half g_k16[NWIN * HEADS * WS2 * HD];
__device__ __half g_v16[NWIN * HEADS * WS2 * HD];
__device__ __half g_at16[NTOK * DIM];

// ---------------- helpers ---------------------------------------------------
__device__ __forceinline__ uint32_t smem_u32(const void* p) {
    uint32_t a;
    asm("{ .reg .u64 t; cvta.to.shared.u64 t, %1; cvt.u32.u64 %0, t; }"
        : "=r"(a) : "l"(p));
    return a;
}
__device__ __forceinline__ void ldsm4(uint32_t& r0, uint32_t& r1,
                                      uint32_t& r2, uint32_t& r3, uint32_t a) {
    asm volatile("ldmatrix.sync.aligned.m8n8.x4.shared.b16 {%0,%1,%2,%3}, [%4];"
                 : "=r"(r0), "=r"(r1), "=r"(r2), "=r"(r3) : "r"(a));
}
__device__ __forceinline__ void ldsm4t(uint32_t& r0, uint32_t& r1,
                                       uint32_t& r2, uint32_t& r3, uint32_t a) {
    asm volatile("ldmatrix.sync.aligned.m8n8.x4.trans.shared.b16 {%0,%1,%2,%3}, [%4];"
                 : "=r"(r0), "=r"(r1), "=r"(r2), "=r"(r3) : "r"(a));
}
#define MMA16816(c, a, b)                                                  \
    asm volatile("mma.sync.aligned.m16n8k16.row.col.f32.f16.f16.f32 "      \
        "{%0,%1,%2,%3}, {%4,%5,%6,%7}, {%8,%9}, {%0,%1,%2,%3};"            \
        : "+f"((c)[0]), "+f"((c)[1]), "+f"((c)[2]), "+f"((c)[3])           \
        : "r"((a)[0]), "r"((a)[1]), "r"((a)[2]), "r"((a)[3]),              \
          "r"((b)[0]), "r"((b)[1]))

#define CP_ASYNC16(dst, src) \
    asm volatile("cp.async.cg.shared.global [%0], [%1], 16;" \
                 :: "r"(dst), "l"(src) : "memory")
#define CP_COMMIT() asm volatile("cp.async.commit_group;" ::: "memory")
#define CP_WAIT0()  asm volatile("cp.async.wait_group 0;" ::: "memory")

__device__ __forceinline__ uint32_t packh2(float x, float y) {
    __half2 h = __floats2half2_rn(x, y);
    return *(uint32_t*)&h;
}

// ---------------- index map (roll -4,-4 + window split) --------------------
__device__ __forceinline__ int src_offset(int R) {
    int w = R >> 6, t = R & 63;
    int b = w >> 6, widx = w & 63;
    int wy = widx >> 3, wx = widx & 7;
    int ty = t >> 3, tx = t & 7;
    int ys = ((wy << 3) + ty + 4) & 63;
    int xs = ((wx << 3) + tx + 4) & 63;
    return ((b << 12) + (ys << 6) + xs) * DIM;
}

// ---------------- fp32 -> fp16 convert (weights only) ----------------------
__global__ __launch_bounds__(256) void conv16(
    const float* __restrict__ src, __half* __restrict__ dst, int n4)
{
    int i = blockIdx.x * 256 + threadIdx.x;
    if (i >= n4) return;
    float4 v = ((const float4*)src)[i];
    ((uint32_t*)dst)[2 * i + 0] = packh2(v.x, v.y);
    ((uint32_t*)dst)[2 * i + 1] = packh2(v.z, v.w);
}

// ---------------------------------------------------------------------------
// fp16 HMMA GEMM. CTA M=128, n-tiles of 128; 8 warps, warp tile 32x64
// (m0 = (wid&3)*32, n0 = (wid>>2)*64). K32 chunks, 2-buffer cp.async,
// one __syncthreads per chunk. 2 CTAs/SM.
// ---------------------------------------------------------------------------
#define A_STR   264
#define B_STR   40
#define A_OFF   1024
#define A_SZ    67584                      // 128*264*2
#define B_OFF   (A_OFF + A_SZ)             // 68608
#define B_BUF   10240                      // 128*40*2
#define SMEM_SZ (B_OFF + 2 * B_BUF)        // 89088

template <int MODE>
__global__ __launch_bounds__(256, 2) void gemm_tc(
    const float* __restrict__ Af,
    const __half* __restrict__ A16,
    const __half* __restrict__ B16,
    const float* __restrict__ bias, float* __restrict__ outp)
{
    constexpr int NTILES = (MODE == 0) ? 6 : 2;
    constexpr int TOTCH  = NTILES * 8;     // K32 chunks
    extern __shared__ char smem[];
    const uint32_t sbase = smem_u32(smem);
    const int tid  = threadIdx.x;
    const int wid  = tid >> 5;
    const int lane = tid & 31;
    const int bx   = blockIdx.x;
    const int m0 = (wid & 3) * 32;          // 4 M-warps
    const int n0 = (wid >> 2) * 64;         // 2 N-warps

    int* rowOff = (int*)smem;
    if (tid < 128) {
        int R = bx * 128 + tid;
        rowOff[tid] = (MODE == 0) ? src_offset(R) : R * DIM;
    }
    __syncthreads();

    // ---- A tile into SMEM (fp16, 128 rows, full K, stride 264) ----
    if (MODE == 0) {
#pragma unroll
        for (int i = 0; i < 32; i++) {
            int idx = tid + i * 256;          // 8192 float4
            int u = idx & 63;
            int r = idx >> 6;
            float4 v = *(const float4*)(Af + rowOff[r] + u * 4);
            uint2 p = make_uint2(packh2(v.x, v.y), packh2(v.z, v.w));
            *(uint2*)(smem + A_OFF + (r * A_STR + u * 4) * 2) = p;
        }
    } else {
#pragma unroll
        for (int i = 0; i < 16; i++) {
            int idx = tid + i * 256;          // 4096 uint4
            int u = idx & 31;
            int r = idx >> 5;
            uint4 v = *(const uint4*)(A16 + rowOff[r] + u * 8);
            *(uint4*)(smem + A_OFF + (r * A_STR + u * 8) * 2) = v;
        }
    }

    // ---- B chunk loader via cp.async: chunk gg -> buffer b ----
    auto loadB = [&](int gg, int b) {
        const int nb = (gg >> 3) * 128;
        const int kk = (gg & 7) * 32;
#pragma unroll
        for (int i = 0; i < 2; i++) {
            int idx = tid + i * 256;          // 512 x 16B
            int r = idx >> 2, u = idx & 3;
            const __half* s = B16 + (nb + r) * DIM + kk + u * 8;
            uint32_t d = sbase + B_OFF + b * B_BUF + (r * B_STR + u * 8) * 2;
            CP_ASYNC16(d, s);
        }
        CP_COMMIT();
    };

    loadB(0, 0);
    CP_WAIT0();
    __syncthreads();

    const int a_row = lane & 15;
    const int a_col = (lane >> 4) * 8;
    const int b_row = (lane & 7) + ((lane >> 4) << 3);
    const int b_col = ((lane >> 3) & 1) * 8;
    const uint32_t aAddr = sbase + A_OFF + ((m0 + a_row) * A_STR + a_col) * 2;

    float acc[2][8][4];
#pragma unroll
    for (int mf = 0; mf < 2; mf++)
#pragma unroll
        for (int nf = 0; nf < 8; nf++)
#pragma unroll
            for (int q = 0; q < 4; q++) acc[mf][nf][q] = 0.f;

#pragma unroll 1
    for (int g = 0; g < TOTCH; g++) {
        const int c  = g & 7;
        const int nt = g >> 3;

        if (g + 1 < TOTCH) loadB(g + 1, (g + 1) & 1);

        // ---- compute chunk g ----
        const uint32_t bBase = sbase + B_OFF + (g & 1) * B_BUF;
#pragma unroll
        for (int ks = 0; ks < 2; ks++) {
            const int kk = c * 32 + ks * 16;
            uint32_t ah[2][4], bh[8][2];
#pragma unroll
            for (int mf = 0; mf < 2; mf++)
                ldsm4(ah[mf][0], ah[mf][1], ah[mf][2], ah[mf][3],
                      aAddr + (mf * 16 * A_STR + kk) * 2);
#pragma unroll
            for (int nf2 = 0; nf2 < 4; nf2++) {
                uint32_t ba = bBase +
                    ((n0 + nf2 * 16 + b_row) * B_STR + ks * 16 + b_col) * 2;
                ldsm4(bh[2 * nf2][0], bh[2 * nf2][1],
                      bh[2 * nf2 + 1][0], bh[2 * nf2 + 1][1], ba);
            }
#pragma unroll
            for (int mf = 0; mf < 2; mf++)
#pragma unroll
                for (int nf = 0; nf < 8; nf++)
                    MMA16816(acc[mf][nf], ah[mf], bh[nf]);
        }

        // ---- epilogue at end of each n-tile ----
        if (c == 7) {
            const int erow = lane >> 2;
            const int ecol = (lane & 3) * 2;
            if (MODE == 0) {
                const int bsel = (nt * 128 + n0) >> 8;   // uniform per warp
                __half* dst = (bsel == 0) ? g_q16 : (bsel == 1) ? g_k16 : g_v16;
#pragma unroll
                for (int mf = 0; mf < 2; mf++) {
                    int R0 = bx * 128 + m0 + mf * 16 + erow;
                    int w0 = R0 >> 6, t0 = R0 & 63;
                    int R1 = R0 + 8;
                    int w1 = R1 >> 6, t1 = R1 & 63;
#pragma unroll
                    for (int nf = 0; nf < 8; nf++) {
                        int jg = nt * 128 + n0 + nf * 8 + ecol;
                        float bx0 = __ldg(&bias[jg]);
                        float bx1 = __ldg(&bias[jg + 1]);
                        int rem = jg & 255;
                        int h = rem >> 5, d = rem & 31;
                        int off0 = (((w0 << 3) + h) * WS2 + t0) * HD + d;
                        *(uint32_t*)&dst[off0] =
                            packh2(acc[mf][nf][0] + bx0, acc[mf][nf][1] + bx1);
                        int off1 = (((w1 << 3) + h) * WS2 + t1) * HD + d;
                        *(uint32_t*)&dst[off1] =
                            packh2(acc[mf][nf][2] + bx0, acc[mf][nf][3] + bx1);
                    }
                }
            } else {
#pragma unroll
                for (int mf = 0; mf < 2; mf++) {
                    int R0 = bx * 128 + m0 + mf * 16 + erow;
                    int so0 = src_offset(R0);
                    int so1 = src_offset(R0 + 8);
#pragma unroll
                    for (int nf = 0; nf < 8; nf++) {
                        int jg = nt * 128 + n0 + nf * 8 + ecol;
                        float bx0 = __ldg(&bias[jg]);
                        float bx1 = __ldg(&bias[jg + 1]);
                        *(float2*)&outp[so0 + jg] =
                            make_float2(acc[mf][nf][0] + bx0, acc[mf][nf][1] + bx1);
                        *(float2*)&outp[so1 + jg] =
                            make_float2(acc[mf][nf][2] + bx0, acc[mf][nf][3] + bx1);
                    }
                }
            }
#pragma unroll
            for (int mf = 0; mf < 2; mf++)
#pragma unroll
                for (int nf = 0; nf < 8; nf++)
#pragma unroll
                    for (int q = 0; q < 4; q++) acc[mf][nf][q] = 0.f;
        }

        CP_WAIT0();
        __syncthreads();
    }
}

// ---------------------------------------------------------------------------
// fp16 HMMA attention. Block = 1 window x 2 heads, 4 warps; 4 CTAs/SM.
// Softmax: separable bias index, mask path branched out for interior windows.
// ---------------------------------------------------------------------------
#define QSTR 40
#define T_SZ 10240
#define AQ  0
#define AK  (1 * T_SZ)
#define AV  (2 * T_SZ)
#define APS (3 * T_SZ)
#define ARG (APS + 1800)
#define ATT_SMEM (ARG + 256)

__global__ __launch_bounds__(128, 4) void attn_mma(const float* __restrict__ pos_enc)
{
    extern __shared__ char smem[];
    const uint32_t sbase = smem_u32(smem);
    const int w    = blockIdx.x;
    const int hp   = blockIdx.y;
    const int tid  = threadIdx.x;
    const int wid  = tid >> 5;
    const int lane = tid & 31;
    const int hl2  = wid >> 1;
    const int m0   = (wid & 1) * 32;
    const int widx = w & 63;
    const bool use_mask = (widx >= 56) || ((widx & 7) == 7);

    {
        const int whbase = ((w << 3) + (hp << 1)) * WS2 * HD;
#pragma unroll
        for (int tz = 0; tz < 3; tz++) {
            const __half* base = (tz == 0) ? g_q16 : (tz == 1) ? g_k16 : g_v16;
#pragma unroll
            for (int j = 0; j < 4; j++) {
                int idx = tid + j * 128;
                int u = idx & 3, r = (idx >> 2) & 63, hh = idx >> 8;
                uint4 v = *(const uint4*)(base + whbase +
                                          (hh * WS2 + r) * HD + u * 8);
                *(uint4*)(smem + tz * T_SZ + ((hh * 64 + r) * QSTR + u * 8) * 2) = v;
            }
        }
        float* psf = (float*)(smem + APS);
        for (int i = tid; i < 450; i += 128)
            psf[i] = pos_enc[(hp * 2) * 225 + i];
        int* rgp = (int*)(smem + ARG);
        if (tid < 64) {
            int wy = widx >> 3, wx = widx & 7;
            int ry = (wy < 7) ? 0 : ((tid >> 3) < 4 ? 1 : 2);
            int rx = (wx < 7) ? 0 : ((tid & 7) < 4 ? 1 : 2);
            rgp[tid] = ry * 3 + rx;
        }
    }
    __syncthreads();

    const float* ps = (const float*)(smem + APS) + hl2 * 225;
    const int* rg = (const int*)(smem + ARG);

    // ---- QK^T ----
    float s[2][8][4];
#pragma unroll
    for (int mf = 0; mf < 2; mf++)
#pragma unroll
        for (int nf = 0; nf < 8; nf++)
#pragma unroll
            for (int q = 0; q < 4; q++) s[mf][nf][q] = 0.f;

    const int a_row = lane & 15;
    const int a_col = (lane >> 4) * 8;
    const int b_row = (lane & 7) + ((lane >> 4) << 3);
    const int b_col = ((lane >> 3) & 1) * 8;
    const uint32_t qA = sbase + AQ + ((hl2 * 64 + m0 + a_row) * QSTR + a_col) * 2;
    const uint32_t kB = sbase + AK + ((hl2 * 64 + b_row) * QSTR + b_col) * 2;

#pragma unroll
    for (int ks = 0; ks < 2; ks++) {
        uint32_t ah[2][4], bh[8][2];
#pragma unroll
        for (int mf = 0; mf < 2; mf++)
            ldsm4(ah[mf][0], ah[mf][1], ah[mf][2], ah[mf][3],
                  qA + (mf * 16 * QSTR + ks * 16) * 2);
#pragma unroll
        for (int nf2 = 0; nf2 < 4; nf2++) {
            uint32_t b = kB + (nf2 * 16 * QSTR + ks * 16) * 2;
            ldsm4(bh[2 * nf2][0], bh[2 * nf2][1],
                  bh[2 * nf2 + 1][0], bh[2 * nf2 + 1][1], b);
        }
#pragma unroll
        for (int mf = 0; mf < 2; mf++)
#pragma unroll
            for (int nf = 0; nf < 8; nf++)
                MMA16816(s[mf][nf], ah[mf], bh[nf]);
    }

    // ---- bias + (mask) + softmax ----
    // ps index is separable: idx = rowconst - (y2*15+x2),
    // rowconst = (y1+7)*15 + (x1+7).
    const int rowl = lane >> 2;
    const int colb = (lane & 3) * 2;
#pragma unroll
    for (int mf = 0; mf < 2; mf++) {
        int t1a = m0 + mf * 16 + rowl, t1b = t1a + 8;
        int rca = ((t1a >> 3) + 7) * 15 + (t1a & 7) + 7;
        int rcb = ((t1b >> 3) + 7) * 15 + (t1b & 7) + 7;
        float mxa = -1e30f, mxb = -1e30f;
        if (use_mask) {
            int rga = rg[t1a], rgb = rg[t1b];
#pragma unroll
            for (int nf = 0; nf < 8; nf++)
#pragma unroll
                for (int e = 0; e < 2; e++) {
                    int t2 = nf * 8 + colb + e;
                    int cc = (t2 >> 3) * 15 + (t2 & 7);
                    int rgc = rg[t2];
                    float va = fmaf(s[mf][nf][e], ATT_SCALE, ps[rca - cc]);
                    float vb = fmaf(s[mf][nf][2 + e], ATT_SCALE, ps[rcb - cc]);
                    if (rgc != rga) va = -1e30f;
                    if (rgc != rgb) vb = -1e30f;
                    s[mf][nf][e] = va;
                    s[mf][nf][2 + e] = vb;
                    mxa = fmaxf(mxa, va);
                    mxb = fmaxf(mxb, vb);
                }
        } else {
#pragma unroll
            for (int nf = 0; nf < 8; nf++)
#pragma unroll
                for (int e = 0; e < 2; e++) {
                    int t2 = nf * 8 + colb + e;
                    int cc = (t2 >> 3) * 15 + (t2 & 7);
                    float va = fmaf(s[mf][nf][e], ATT_SCALE, ps[rca - cc]);
                    float vb = fmaf(s[mf][nf][2 + e], ATT_SCALE, ps[rcb - cc]);
                    s[mf][nf][e] = va;
                    s[mf][nf][2 + e] = vb;
                    mxa = fmaxf(mxa, va);
                    mxb = fmaxf(mxb, vb);
                }
        }
        mxa = fmaxf(mxa, __shfl_xor_sync(0xffffffffu, mxa, 1));
        mxa = fmaxf(mxa, __shfl_xor_sync(0xffffffffu, mxa, 2));
        mxb = fmaxf(mxb, __shfl_xor_sync(0xffffffffu, mxb, 1));
        mxb = fmaxf(mxb, __shfl_xor_sync(0xffffffffu, mxb, 2));
        float sma = 0.f, smb = 0.f;
#pragma unroll
        for (int nf = 0; nf < 8; nf++)
#pragma unroll
            for (int e = 0; e < 2; e++) {
                float ea = __expf(s[mf][nf][e] - mxa);
                float eb = __expf(s[mf][nf][2 + e] - mxb);
                s[mf][nf][e] = ea;
                s[mf][nf][2 + e] = eb;
                sma += ea;
                smb += eb;
            }
        sma += __shfl_xor_sync(0xffffffffu, sma, 1);
        sma += __shfl_xor_sync(0xffffffffu, sma, 2);
        smb += __shfl_xor_sync(0xffffffffu, smb, 1);
        smb += __shfl_xor_sync(0xffffffffu, smb, 2);
        float ia = 1.0f / sma, ib = 1.0f / smb;
#pragma unroll
        for (int nf = 0; nf < 8; nf++) {
            s[mf][nf][0] *= ia; s[mf][nf][1] *= ia;
            s[mf][nf][2] *= ib; s[mf][nf][3] *= ib;
        }
    }

    // ---- PV ----
    float o[2][4][4];
#pragma unroll
    for (int mf = 0; mf < 2; mf++)
#pragma unroll
        for (int nf = 0; nf < 4; nf++)
#pragma unroll
            for (int q = 0; q < 4; q++) o[mf][nf][q] = 0.f;

    const int v_row = (lane & 7) + ((lane >> 3) & 1) * 8;
    const int v_col = (lane >> 4) * 8;
#pragma unroll
    for (int kf = 0; kf < 4; kf++) {
        uint32_t aP[2][4];
#pragma unroll
        for (int mf = 0; mf < 2; mf++) {
            aP[mf][0] = packh2(s[mf][2 * kf][0],     s[mf][2 * kf][1]);
            aP[mf][1] = packh2(s[mf][2 * kf][2],     s[mf][2 * kf][3]);
            aP[mf][2] = packh2(s[mf][2 * kf + 1][0], s[mf][2 * kf + 1][1]);
            aP[mf][3] = packh2(s[mf][2 * kf + 1][2], s[mf][2 * kf + 1][3]);
        }
        uint32_t bV[4][2];
#pragma unroll
        for (int dh = 0; dh < 2; dh++) {
            uint32_t a = sbase + AV +
                ((hl2 * 64 + kf * 16 + v_row) * QSTR + dh * 16 + v_col) * 2;
            ldsm4t(bV[2 * dh][0], bV[2 * dh][1],
                   bV[2 * dh + 1][0], bV[2 * dh + 1][1], a);
        }
#pragma unroll
        for (int mf = 0; mf < 2; mf++)
#pragma unroll
            for (int nf = 0; nf < 4; nf++)
                MMA16816(o[mf][nf], aP[mf], bV[nf]);
    }

    // ---- epilogue: fp16 output [token][c] ----
    const int head = hp * 2 + hl2;
#pragma unroll
    for (int mf = 0; mf < 2; mf++) {
        int t1a = m0 + mf * 16 + rowl, t1b = t1a + 8;
#pragma unroll
        for (int nf = 0; nf < 4; nf++) {
            int gcol = head * 32 + nf * 8 + colb;
            *(uint32_t*)&g_at16[(w * WS2 + t1a) * DIM + gcol] =
                packh2(o[mf][nf][0], o[mf][nf][1]);
            *(uint32_t*)&g_at16[(w * WS2 + t1b) * DIM + gcol] =
                packh2(o[mf][nf][2], o[mf][nf][3]);
        }
    }
}

// ---------------------------------------------------------------------------
extern "C" void kernel_launch(void* const* d_in, const int* in_sizes, int n_in,
                              void* d_out, int out_size)
{
    const float* x       = (const float*)d_in[0];
    const float* w_qkv   = (const float*)d_in[1];
    const float* b_qkv   = (const float*)d_in[2];
    const float* w_out   = (const float*)d_in[3];
    const float* b_out   = (const float*)d_in[4];
    const float* pos_enc = (const float*)d_in[5];
    float* out = (float*)d_out;

    cudaFuncSetAttribute(gemm_tc<0>, cudaFuncAttributeMaxDynamicSharedMemorySize, SMEM_SZ);
    cudaFuncSetAttribute(gemm_tc<1>, cudaFuncAttributeMaxDynamicSharedMemorySize, SMEM_SZ);
    cudaFuncSetAttribute(attn_mma, cudaFuncAttributeMaxDynamicSharedMemorySize, ATT_SMEM);

    __half *wq16, *wo16, *at16;
    cudaGetSymbolAddress((void**)&wq16, g_wq16);
    cudaGetSymbolAddress((void**)&wo16, g_wo16);
    cudaGetSymbolAddress((void**)&at16, g_at16);

    conv16<<<(768 * DIM / 4 + 255) / 256, 256>>>(w_qkv, wq16, 768 * DIM / 4);
    conv16<<<(DIM * DIM / 4 + 255) / 256, 256>>>(w_out, wo16, DIM * DIM / 4);

    gemm_tc<0><<<NTOK / 128, 256, SMEM_SZ>>>(x, nullptr, wq16, b_qkv, nullptr);
    attn_mma<<<dim3(NWIN, 4), 128, ATT_SMEM>>>(pos_enc);
    gemm_tc<1><<<NTOK / 128, 256, SMEM_SZ>>>(nullptr, at16, wo16, b_out, out);
}

// round 14
// speedup vs baseline: 2.3232x; 1.0902x over previous
#include <cuda_runtime.h>
#include <cuda_fp16.h>
#include <cstdint>

// ---------------------------------------------------------------------------
// ShiftedWindowAttention — round 14: fp16 HMMA, K64 chunks (half the barriers),
// warp tile 32x64, 2 CTAs/SM; merged weight conversion; attention unchanged.
// ---------------------------------------------------------------------------

#define NWIN   2048
#define NTOK   131072
#define HEADS  8
#define HD     32
#define WS2    64
#define DIM    256
#define ATT_SCALE 0.17677669529663687f

// ---------------- scratch ---------------------------------------------------
__device__ __half g_wq16[768 * DIM];
__device__ __half g_wo16[DIM * DIM];
__device__ __half g_q16[NWIN * HEADS * WS2 * HD];
__device__ __half g_k16[NWIN * HEADS * WS2 * HD];
__device__ __half g_v16[NWIN * HEADS * WS2 * HD];
__device__ __half g_at16[NTOK * DIM];

// ---------------- helpers ---------------------------------------------------
__device__ __forceinline__ uint32_t smem_u32(const void* p) {
    uint32_t a;
    asm("{ .reg .u64 t; cvta.to.shared.u64 t, %1; cvt.u32.u64 %0, t; }"
        : "=r"(a) : "l"(p));
    return a;
}
__device__ __forceinline__ void ldsm4(uint32_t& r0, uint32_t& r1,
                                      uint32_t& r2, uint32_t& r3, uint32_t a) {
    asm volatile("ldmatrix.sync.aligned.m8n8.x4.shared.b16 {%0,%1,%2,%3}, [%4];"
                 : "=r"(r0), "=r"(r1), "=r"(r2), "=r"(r3) : "r"(a));
}
__device__ __forceinline__ void ldsm4t(uint32_t& r0, uint32_t& r1,
                                       uint32_t& r2, uint32_t& r3, uint32_t a) {
    asm volatile("ldmatrix.sync.aligned.m8n8.x4.trans.shared.b16 {%0,%1,%2,%3}, [%4];"
                 : "=r"(r0), "=r"(r1), "=r"(r2), "=r"(r3) : "r"(a));
}
#define MMA16816(c, a, b)                                                  \
    asm volatile("mma.sync.aligned.m16n8k16.row.col.f32.f16.f16.f32 "      \
        "{%0,%1,%2,%3}, {%4,%5,%6,%7}, {%8,%9}, {%0,%1,%2,%3};"            \
        : "+f"((c)[0]), "+f"((c)[1]), "+f"((c)[2]), "+f"((c)[3])           \
        : "r"((a)[0]), "r"((a)[1]), "r"((a)[2]), "r"((a)[3]),              \
          "r"((b)[0]), "r"((b)[1]))

#define CP_ASYNC16(dst, src) \
    asm volatile("cp.async.cg.shared.global [%0], [%1], 16;" \
                 :: "r"(dst), "l"(src) : "memory")
#define CP_COMMIT() asm volatile("cp.async.commit_group;" ::: "memory")
#define CP_WAIT0()  asm volatile("cp.async.wait_group 0;" ::: "memory")

__device__ __forceinline__ uint32_t packh2(float x, float y) {
    __half2 h = __floats2half2_rn(x, y);
    return *(uint32_t*)&h;
}

// ---------------- index map (roll -4,-4 + window split) --------------------
__device__ __forceinline__ int src_offset(int R) {
    int w = R >> 6, t = R & 63;
    int b = w >> 6, widx = w & 63;
    int wy = widx >> 3, wx = widx & 7;
    int ty = t >> 3, tx = t & 7;
    int ys = ((wy << 3) + ty + 4) & 63;
    int xs = ((wx << 3) + tx + 4) & 63;
    return ((b << 12) + (ys << 6) + xs) * DIM;
}

// ---------------- fp32 -> fp16 convert (both weights, one launch) ----------
#define NQ1 49152   // 768*256/4
#define NQ2 16384   // 256*256/4
__global__ __launch_bounds__(256) void conv16_all(
    const float* __restrict__ wq, const float* __restrict__ wo)
{
    int i = blockIdx.x * 256 + threadIdx.x;
    const float* src;
    __half* dst;
    int j;
    if (i < NQ1) { src = wq; dst = g_wq16; j = i; }
    else         { src = wo; dst = g_wo16; j = i - NQ1; }
    float4 v = ((const float4*)src)[j];
    ((uint32_t*)dst)[2 * j + 0] = packh2(v.x, v.y);
    ((uint32_t*)dst)[2 * j + 1] = packh2(v.z, v.w);
}

// ---------------------------------------------------------------------------
// fp16 HMMA GEMM. CTA M=128, n-tiles of 128; 8 warps, warp tile 32x64.
// K64 chunks (4 k-steps of 16), 2-buffer cp.async, ONE sync per K64 chunk.
// B buffer row: 64 elems + 8 pad (stride 72 = 144B). 2 CTAs/SM.
// ---------------------------------------------------------------------------
#define A_STR   264
#define B_STR   72
#define A_OFF   1024
#define A_SZ    67584                      // 128*264*2
#define B_OFF   (A_OFF + A_SZ)             // 68608
#define B_BUF   18432                      // 128*72*2
#define SMEM_SZ (B_OFF + 2 * B_BUF)        // 105472

template <int MODE>
__global__ __launch_bounds__(256, 2) void gemm_tc(
    const float* __restrict__ Af,
    const __half* __restrict__ A16,
    const __half* __restrict__ B16,
    const float* __restrict__ bias, float* __restrict__ outp)
{
    constexpr int NTILES = (MODE == 0) ? 6 : 2;
    constexpr int TOTCH  = NTILES * 4;     // K64 chunks
    extern __shared__ char smem[];
    const uint32_t sbase = smem_u32(smem);
    const int tid  = threadIdx.x;
    const int wid  = tid >> 5;
    const int lane = tid & 31;
    const int bx   = blockIdx.x;
    const int m0 = (wid & 3) * 32;          // 4 M-warps
    const int n0 = (wid >> 2) * 64;         // 2 N-warps

    int* rowOff = (int*)smem;
    if (tid < 128) {
        int R = bx * 128 + tid;
        rowOff[tid] = (MODE == 0) ? src_offset(R) : R * DIM;
    }
    __syncthreads();

    // ---- A tile into SMEM (fp16, 128 rows, full K, stride 264) ----
    if (MODE == 0) {
#pragma unroll
        for (int i = 0; i < 32; i++) {
            int idx = tid + i * 256;          // 8192 float4
            int u = idx & 63;
            int r = idx >> 6;
            float4 v = *(const float4*)(Af + rowOff[r] + u * 4);
            uint2 p = make_uint2(packh2(v.x, v.y), packh2(v.z, v.w));
            *(uint2*)(smem + A_OFF + (r * A_STR + u * 4) * 2) = p;
        }
    } else {
#pragma unroll
        for (int i = 0; i < 16; i++) {
            int idx = tid + i * 256;          // 4096 uint4
            int u = idx & 31;
            int r = idx >> 5;
            uint4 v = *(const uint4*)(A16 + rowOff[r] + u * 8);
            *(uint4*)(smem + A_OFF + (r * A_STR + u * 8) * 2) = v;
        }
    }

    // ---- B chunk loader (K64) via cp.async: chunk gg -> buffer b ----
    auto loadB = [&](int gg, int b) {
        const int nb = (gg >> 2) * 128;
        const int kk = (gg & 3) * 64;
#pragma unroll
        for (int i = 0; i < 4; i++) {
            int idx = tid + i * 256;          // 1024 x 16B
            int r = idx >> 3, u = idx & 7;
            const __half* s = B16 + (nb + r) * DIM + kk + u * 8;
            uint32_t d = sbase + B_OFF + b * B_BUF + (r * B_STR + u * 8) * 2;
            CP_ASYNC16(d, s);
        }
        CP_COMMIT();
    };

    loadB(0, 0);
    CP_WAIT0();
    __syncthreads();

    const int a_row = lane & 15;
    const int a_col = (lane >> 4) * 8;
    const int b_row = (lane & 7) + ((lane >> 4) << 3);
    const int b_col = ((lane >> 3) & 1) * 8;
    const uint32_t aAddr = sbase + A_OFF + ((m0 + a_row) * A_STR + a_col) * 2;

    float acc[2][8][4];
#pragma unroll
    for (int mf = 0; mf < 2; mf++)
#pragma unroll
        for (int nf = 0; nf < 8; nf++)
#pragma unroll
            for (int q = 0; q < 4; q++) acc[mf][nf][q] = 0.f;

#pragma unroll 1
    for (int g = 0; g < TOTCH; g++) {
        const int c  = g & 3;
        const int nt = g >> 2;

        if (g + 1 < TOTCH) loadB(g + 1, (g + 1) & 1);

        // ---- compute chunk g (K64 = 4 k-steps of 16) ----
        const uint32_t bBase = sbase + B_OFF + (g & 1) * B_BUF;
#pragma unroll
        for (int ks = 0; ks < 4; ks++) {
            const int kkA = c * 64 + ks * 16;
            uint32_t ah[2][4], bh[8][2];
#pragma unroll
            for (int mf = 0; mf < 2; mf++)
                ldsm4(ah[mf][0], ah[mf][1], ah[mf][2], ah[mf][3],
                      aAddr + (mf * 16 * A_STR + kkA) * 2);
#pragma unroll
            for (int nf2 = 0; nf2 < 4; nf2++) {
                uint32_t ba = bBase +
                    ((n0 + nf2 * 16 + b_row) * B_STR + ks * 16 + b_col) * 2;
                ldsm4(bh[2 * nf2][0], bh[2 * nf2][1],
                      bh[2 * nf2 + 1][0], bh[2 * nf2 + 1][1], ba);
            }
#pragma unroll
            for (int mf = 0; mf < 2; mf++)
#pragma unroll
                for (int nf = 0; nf < 8; nf++)
                    MMA16816(acc[mf][nf], ah[mf], bh[nf]);
        }

        // ---- epilogue at end of each n-tile ----
        if (c == 3) {
            const int erow = lane >> 2;
            const int ecol = (lane & 3) * 2;
            if (MODE == 0) {
                const int bsel = (nt * 128 + n0) >> 8;   // uniform per warp
                __half* dst = (bsel == 0) ? g_q16 : (bsel == 1) ? g_k16 : g_v16;
#pragma unroll
                for (int mf = 0; mf < 2; mf++) {
                    int R0 = bx * 128 + m0 + mf * 16 + erow;
                    int w0 = R0 >> 6, t0 = R0 & 63;
                    int R1 = R0 + 8;
                    int w1 = R1 >> 6, t1 = R1 & 63;
#pragma unroll
                    for (int nf = 0; nf < 8; nf++) {
                        int jg = nt * 128 + n0 + nf * 8 + ecol;
                        float bx0 = __ldg(&bias[jg]);
                        float bx1 = __ldg(&bias[jg + 1]);
                        int rem = jg & 255;
                        int h = rem >> 5, d = rem & 31;
                        int off0 = (((w0 << 3) + h) * WS2 + t0) * HD + d;
                        *(uint32_t*)&dst[off0] =
                            packh2(acc[mf][nf][0] + bx0, acc[mf][nf][1] + bx1);
                        int off1 = (((w1 << 3) + h) * WS2 + t1) * HD + d;
                        *(uint32_t*)&dst[off1] =
                            packh2(acc[mf][nf][2] + bx0, acc[mf][nf][3] + bx1);
                    }
                }
            } else {
#pragma unroll
                for (int mf = 0; mf < 2; mf++) {
                    int R0 = bx * 128 + m0 + mf * 16 + erow;
                    int so0 = src_offset(R0);
                    int so1 = src_offset(R0 + 8);
#pragma unroll
                    for (int nf = 0; nf < 8; nf++) {
                        int jg = nt * 128 + n0 + nf * 8 + ecol;
                        float bx0 = __ldg(&bias[jg]);
                        float bx1 = __ldg(&bias[jg + 1]);
                        *(float2*)&outp[so0 + jg] =
                            make_float2(acc[mf][nf][0] + bx0, acc[mf][nf][1] + bx1);
                        *(float2*)&outp[so1 + jg] =
                            make_float2(acc[mf][nf][2] + bx0, acc[mf][nf][3] + bx1);
                    }
                }
            }
#pragma unroll
            for (int mf = 0; mf < 2; mf++)
#pragma unroll
                for (int nf = 0; nf < 8; nf++)
#pragma unroll
                    for (int q = 0; q < 4; q++) acc[mf][nf][q] = 0.f;
        }

        CP_WAIT0();
        __syncthreads();
    }
}

// ---------------------------------------------------------------------------
// fp16 HMMA attention (unchanged from round 13).
// ---------------------------------------------------------------------------
#define QSTR 40
#define T_SZ 10240
#define AQ  0
#define AK  (1 * T_SZ)
#define AV  (2 * T_SZ)
#define APS (3 * T_SZ)
#define ARG (APS + 1800)
#define ATT_SMEM (ARG + 256)

__global__ __launch_bounds__(128, 4) void attn_mma(const float* __restrict__ pos_enc)
{
    extern __shared__ char smem[];
    const uint32_t sbase = smem_u32(smem);
    const int w    = blockIdx.x;
    const int hp   = blockIdx.y;
    const int tid  = threadIdx.x;
    const int wid  = tid >> 5;
    const int lane = tid & 31;
    const int hl2  = wid >> 1;
    const int m0   = (wid & 1) * 32;
    const int widx = w & 63;
    const bool use_mask = (widx >= 56) || ((widx & 7) == 7);

    {
        const int whbase = ((w << 3) + (hp << 1)) * WS2 * HD;
#pragma unroll
        for (int tz = 0; tz < 3; tz++) {
            const __half* base = (tz == 0) ? g_q16 : (tz == 1) ? g_k16 : g_v16;
#pragma unroll
            for (int j = 0; j < 4; j++) {
                int idx = tid + j * 128;
                int u = idx & 3, r = (idx >> 2) & 63, hh = idx >> 8;
                uint4 v = *(const uint4*)(base + whbase +
                                          (hh * WS2 + r) * HD + u * 8);
                *(uint4*)(smem + tz * T_SZ + ((hh * 64 + r) * QSTR + u * 8) * 2) = v;
            }
        }
        float* psf = (float*)(smem + APS);
        for (int i = tid; i < 450; i += 128)
            psf[i] = pos_enc[(hp * 2) * 225 + i];
        int* rgp = (int*)(smem + ARG);
        if (tid < 64) {
            int wy = widx >> 3, wx = widx & 7;
            int ry = (wy < 7) ? 0 : ((tid >> 3) < 4 ? 1 : 2);
            int rx = (wx < 7) ? 0 : ((tid & 7) < 4 ? 1 : 2);
            rgp[tid] = ry * 3 + rx;
        }
    }
    __syncthreads();

    const float* ps = (const float*)(smem + APS) + hl2 * 225;
    const int* rg = (const int*)(smem + ARG);

    float s[2][8][4];
#pragma unroll
    for (int mf = 0; mf < 2; mf++)
#pragma unroll
        for (int nf = 0; nf < 8; nf++)
#pragma unroll
            for (int q = 0; q < 4; q++) s[mf][nf][q] = 0.f;

    const int a_row = lane & 15;
    const int a_col = (lane >> 4) * 8;
    const int b_row = (lane & 7) + ((lane >> 4) << 3);
    const int b_col = ((lane >> 3) & 1) * 8;
    const uint32_t qA = sbase + AQ + ((hl2 * 64 + m0 + a_row) * QSTR + a_col) * 2;
    const uint32_t kB = sbase + AK + ((hl2 * 64 + b_row) * QSTR + b_col) * 2;

#pragma unroll
    for (int ks = 0; ks < 2; ks++) {
        uint32_t ah[2][4], bh[8][2];
#pragma unroll
        for (int mf = 0; mf < 2; mf++)
            ldsm4(ah[mf][0], ah[mf][1], ah[mf][2], ah[mf][3],
                  qA + (mf * 16 * QSTR + ks * 16) * 2);
#pragma unroll
        for (int nf2 = 0; nf2 < 4; nf2++) {
            uint32_t b = kB + (nf2 * 16 * QSTR + ks * 16) * 2;
            ldsm4(bh[2 * nf2][0], bh[2 * nf2][1],
                  bh[2 * nf2 + 1][0], bh[2 * nf2 + 1][1], b);
        }
#pragma unroll
        for (int mf = 0; mf < 2; mf++)
#pragma unroll
            for (int nf = 0; nf < 8; nf++)
                MMA16816(s[mf][nf], ah[mf], bh[nf]);
    }

    const int rowl = lane >> 2;
    const int colb = (lane & 3) * 2;
#pragma unroll
    for (int mf = 0; mf < 2; mf++) {
        int t1a = m0 + mf * 16 + rowl, t1b = t1a + 8;
        int rca = ((t1a >> 3) + 7) * 15 + (t1a & 7) + 7;
        int rcb = ((t1b >> 3) + 7) * 15 + (t1b & 7) + 7;
        float mxa = -1e30f, mxb = -1e30f;
        if (use_mask) {
            int rga = rg[t1a], rgb = rg[t1b];
#pragma unroll
            for (int nf = 0; nf < 8; nf++)
#pragma unroll
                for (int e = 0; e < 2; e++) {
                    int t2 = nf * 8 + colb + e;
                    int cc = (t2 >> 3) * 15 + (t2 & 7);
                    int rgc = rg[t2];
                    float va = fmaf(s[mf][nf][e], ATT_SCALE, ps[rca - cc]);
                    float vb = fmaf(s[mf][nf][2 + e], ATT_SCALE, ps[rcb - cc]);
                    if (rgc != rga) va = -1e30f;
                    if (rgc != rgb) vb = -1e30f;
                    s[mf][nf][e] = va;
                    s[mf][nf][2 + e] = vb;
                    mxa = fmaxf(mxa, va);
                    mxb = fmaxf(mxb, vb);
                }
        } else {
#pragma unroll
            for (int nf = 0; nf < 8; nf++)
#pragma unroll
                for (int e = 0; e < 2; e++) {
                    int t2 = nf * 8 + colb + e;
                    int cc = (t2 >> 3) * 15 + (t2 & 7);
                    float va = fmaf(s[mf][nf][e], ATT_SCALE, ps[rca - cc]);
                    float vb = fmaf(s[mf][nf][2 + e], ATT_SCALE, ps[rcb - cc]);
                    s[mf][nf][e] = va;
                    s[mf][nf][2 + e] = vb;
                    mxa = fmaxf(mxa, va);
                    mxb = fmaxf(mxb, vb);
                }
        }
        mxa = fmaxf(mxa, __shfl_xor_sync(0xffffffffu, mxa, 1));
        mxa = fmaxf(mxa, __shfl_xor_sync(0xffffffffu, mxa, 2));
        mxb = fmaxf(mxb, __shfl_xor_sync(0xffffffffu, mxb, 1));
        mxb = fmaxf(mxb, __shfl_xor_sync(0xffffffffu, mxb, 2));
        float sma = 0.f, smb = 0.f;
#pragma unroll
        for (int nf = 0; nf < 8; nf++)
#pragma unroll
            for (int e = 0; e < 2; e++) {
                float ea = __expf(s[mf][nf][e] - mxa);
                float eb = __expf(s[mf][nf][2 + e] - mxb);
                s[mf][nf][e] = ea;
                s[mf][nf][2 + e] = eb;
                sma += ea;
                smb += eb;
            }
        sma += __shfl_xor_sync(0xffffffffu, sma, 1);
        sma += __shfl_xor_sync(0xffffffffu, sma, 2);
        smb += __shfl_xor_sync(0xffffffffu, smb, 1);
        smb += __shfl_xor_sync(0xffffffffu, smb, 2);
        float ia = 1.0f / sma, ib = 1.0f / smb;
#pragma unroll
        for (int nf = 0; nf < 8; nf++) {
            s[mf][nf][0] *= ia; s[mf][nf][1] *= ia;
            s[mf][nf][2] *= ib; s[mf][nf][3] *= ib;
        }
    }

    float o[2][4][4];
#pragma unroll
    for (int mf = 0; mf < 2; mf++)
#pragma unroll
        for (int nf = 0; nf < 4; nf++)
#pragma unroll
            for (int q = 0; q < 4; q++) o[mf][nf][q] = 0.f;

    const int v_row = (lane & 7) + ((lane >> 3) & 1) * 8;
    const int v_col = (lane >> 4) * 8;
#pragma unroll
    for (int kf = 0; kf < 4; kf++) {
        uint32_t aP[2][4];
#pragma unroll
        for (int mf = 0; mf < 2; mf++) {
            aP[mf][0] = packh2(s[mf][2 * kf][0],     s[mf][2 * kf][1]);
            aP[mf][1] = packh2(s[mf][2 * kf][2],     s[mf][2 * kf][3]);
            aP[mf][2] = packh2(s[mf][2 * kf + 1][0], s[mf][2 * kf + 1][1]);
            aP[mf][3] = packh2(s[mf][2 * kf + 1][2], s[mf][2 * kf + 1][3]);
        }
        uint32_t bV[4][2];
#pragma unroll
        for (int dh = 0; dh < 2; dh++) {
            uint32_t a = sbase + AV +
                ((hl2 * 64 + kf * 16 + v_row) * QSTR + dh * 16 + v_col) * 2;
            ldsm4t(bV[2 * dh][0], bV[2 * dh][1],
                   bV[2 * dh + 1][0], bV[2 * dh + 1][1], a);
        }
#pragma unroll
        for (int mf = 0; mf < 2; mf++)
#pragma unroll
            for (int nf = 0; nf < 4; nf++)
                MMA16816(o[mf][nf], aP[mf], bV[nf]);
    }

    const int head = hp * 2 + hl2;
#pragma unroll
    for (int mf = 0; mf < 2; mf++) {
        int t1a = m0 + mf * 16 + rowl, t1b = t1a + 8;
#pragma unroll
        for (int nf = 0; nf < 4; nf++) {
            int gcol = head * 32 + nf * 8 + colb;
            *(uint32_t*)&g_at16[(w * WS2 + t1a) * DIM + gcol] =
                packh2(o[mf][nf][0], o[mf][nf][1]);
            *(uint32_t*)&g_at16[(w * WS2 + t1b) * DIM + gcol] =
                packh2(o[mf][nf][2], o[mf][nf][3]);
        }
    }
}

// ---------------------------------------------------------------------------
extern "C" void kernel_launch(void* const* d_in, const int* in_sizes, int n_in,
                              void* d_out, int out_size)
{
    const float* x       = (const float*)d_in[0];
    const float* w_qkv   = (const float*)d_in[1];
    const float* b_qkv   = (const float*)d_in[2];
    const float* w_out   = (const float*)d_in[3];
    const float* b_out   = (const float*)d_in[4];
    const float* pos_enc = (const float*)d_in[5];
    float* out = (float*)d_out;

    cudaFuncSetAttribute(gemm_tc<0>, cudaFuncAttributeMaxDynamicSharedMemorySize, SMEM_SZ);
    cudaFuncSetAttribute(gemm_tc<1>, cudaFuncAttributeMaxDynamicSharedMemorySize, SMEM_SZ);
    cudaFuncSetAttribute(attn_mma, cudaFuncAttributeMaxDynamicSharedMemorySize, ATT_SMEM);

    __half *wq16, *wo16, *at16;
    cudaGetSymbolAddress((void**)&wq16, g_wq16);
    cudaGetSymbolAddress((void**)&wo16, g_wo16);
    cudaGetSymbolAddress((void**)&at16, g_at16);

    conv16_all<<<(NQ1 + NQ2) / 256, 256>>>(w_qkv, w_out);

    gemm_tc<0><<<NTOK / 128, 256, SMEM_SZ>>>(x, nullptr, wq16, b_qkv, nullptr);
    attn_mma<<<dim3(NWIN, 4), 128, ATT_SMEM>>>(pos_enc);
    gemm_tc<1><<<NTOK / 128, 256, SMEM_SZ>>>(nullptr, at16, wo16, b_out, out);
}

// round 16
// speedup vs baseline: 2.3782x; 1.0237x over previous
#include <cuda_runtime.h>
#include <cuda_fp16.h>
#include <cstdint>

// ---------------------------------------------------------------------------
// ShiftedWindowAttention — round 16: fused attention+out-proj, FIXED smem map
// (phased overlays: at-tile overlays K, B-buffers overlay V; o held packed in
// registers across the phase boundary). qkv GEMM unchanged (round-14 proven).
// ---------------------------------------------------------------------------

#define NWIN   2048
#define NTOK   131072
#define HEADS  8
#define HD     32
#define WS2    64
#define DIM    256
#define ATT_SCALE 0.17677669529663687f

// ---------------- scratch ---------------------------------------------------
__device__ __half g_wq16[768 * DIM];
__device__ __half g_wo16[DIM * DIM];
__device__ __half g_q16[NWIN * HEADS * WS2 * HD];
__device__ __half g_k16[NWIN * HEADS * WS2 * HD];
__device__ __half g_v16[NWIN * HEADS * WS2 * HD];

// ---------------- helpers ---------------------------------------------------
__device__ __forceinline__ uint32_t smem_u32(const void* p) {
    uint32_t a;
    asm("{ .reg .u64 t; cvta.to.shared.u64 t, %1; cvt.u32.u64 %0, t; }"
        : "=r"(a) : "l"(p));
    return a;
}
__device__ __forceinline__ void ldsm4(uint32_t& r0, uint32_t& r1,
                                      uint32_t& r2, uint32_t& r3, uint32_t a) {
    asm volatile("ldmatrix.sync.aligned.m8n8.x4.shared.b16 {%0,%1,%2,%3}, [%4];"
                 : "=r"(r0), "=r"(r1), "=r"(r2), "=r"(r3) : "r"(a));
}
__device__ __forceinline__ void ldsm4t(uint32_t& r0, uint32_t& r1,
                                       uint32_t& r2, uint32_t& r3, uint32_t a) {
    asm volatile("ldmatrix.sync.aligned.m8n8.x4.trans.shared.b16 {%0,%1,%2,%3}, [%4];"
                 : "=r"(r0), "=r"(r1), "=r"(r2), "=r"(r3) : "r"(a));
}
#define MMA16816(c, a, b)                                                  \
    asm volatile("mma.sync.aligned.m16n8k16.row.col.f32.f16.f16.f32 "      \
        "{%0,%1,%2,%3}, {%4,%5,%6,%7}, {%8,%9}, {%0,%1,%2,%3};"            \
        : "+f"((c)[0]), "+f"((c)[1]), "+f"((c)[2]), "+f"((c)[3])           \
        : "r"((a)[0]), "r"((a)[1]), "r"((a)[2]), "r"((a)[3]),              \
          "r"((b)[0]), "r"((b)[1]))

#define CP_ASYNC16(dst, src) \
    asm volatile("cp.async.cg.shared.global [%0], [%1], 16;" \
                 :: "r"(dst), "l"(src) : "memory")
#define CP_COMMIT() asm volatile("cp.async.commit_group;" ::: "memory")
#define CP_WAIT0()  asm volatile("cp.async.wait_group 0;" ::: "memory")

__device__ __forceinline__ uint32_t packh2(float x, float y) {
    __half2 h = __floats2half2_rn(x, y);
    return *(uint32_t*)&h;
}

// ---------------- index map (roll -4,-4 + window split) --------------------
__device__ __forceinline__ int src_offset(int R) {
    int w = R >> 6, t = R & 63;
    int b = w >> 6, widx = w & 63;
    int wy = widx >> 3, wx = widx & 7;
    int ty = t >> 3, tx = t & 7;
    int ys = ((wy << 3) + ty + 4) & 63;
    int xs = ((wx << 3) + tx + 4) & 63;
    return ((b << 12) + (ys << 6) + xs) * DIM;
}

// ---------------- fp32 -> fp16 convert (both weights, one launch) ----------
#define NQ1 49152
#define NQ2 16384
__global__ __launch_bounds__(256) void conv16_all(
    const float* __restrict__ wq, const float* __restrict__ wo)
{
    int i = blockIdx.x * 256 + threadIdx.x;
    const float* src;
    __half* dst;
    int j;
    if (i < NQ1) { src = wq; dst = g_wq16; j = i; }
    else         { src = wo; dst = g_wo16; j = i - NQ1; }
    float4 v = ((const float4*)src)[j];
    ((uint32_t*)dst)[2 * j + 0] = packh2(v.x, v.y);
    ((uint32_t*)dst)[2 * j + 1] = packh2(v.z, v.w);
}

// ---------------------------------------------------------------------------
// qkv GEMM (round-14 proven): fp16 HMMA, M-tile 128, warp 32x64, K64 chunks.
// ---------------------------------------------------------------------------
#define A_STR   264
#define B_STR   72
#define A_OFF   1024
#define A_SZ    67584
#define B_OFF   (A_OFF + A_SZ)
#define B_BUF   18432
#define SMEM_SZ (B_OFF + 2 * B_BUF)

__global__ __launch_bounds__(256, 2) void qkv_gemm(
    const float* __restrict__ Af,
    const __half* __restrict__ B16,
    const float* __restrict__ bias)
{
    constexpr int TOTCH = 24;
    extern __shared__ char smem[];
    const uint32_t sbase = smem_u32(smem);
    const int tid  = threadIdx.x;
    const int wid  = tid >> 5;
    const int lane = tid & 31;
    const int bx   = blockIdx.x;
    const int m0 = (wid & 3) * 32;
    const int n0 = (wid >> 2) * 64;

    int* rowOff = (int*)smem;
    if (tid < 128) rowOff[tid] = src_offset(bx * 128 + tid);
    __syncthreads();

#pragma unroll
    for (int i = 0; i < 32; i++) {
        int idx = tid + i * 256;
        int u = idx & 63;
        int r = idx >> 6;
        float4 v = *(const float4*)(Af + rowOff[r] + u * 4);
        uint2 p = make_uint2(packh2(v.x, v.y), packh2(v.z, v.w));
        *(uint2*)(smem + A_OFF + (r * A_STR + u * 4) * 2) = p;
    }

    auto loadB = [&](int gg, int b) {
        const int nb = (gg >> 2) * 128;
        const int kk = (gg & 3) * 64;
#pragma unroll
        for (int i = 0; i < 4; i++) {
            int idx = tid + i * 256;
            int r = idx >> 3, u = idx & 7;
            const __half* s = B16 + (nb + r) * DIM + kk + u * 8;
            uint32_t d = sbase + B_OFF + b * B_BUF + (r * B_STR + u * 8) * 2;
            CP_ASYNC16(d, s);
        }
        CP_COMMIT();
    };

    loadB(0, 0);
    CP_WAIT0();
    __syncthreads();

    const int a_row = lane & 15;
    const int a_col = (lane >> 4) * 8;
    const int b_row = (lane & 7) + ((lane >> 4) << 3);
    const int b_col = ((lane >> 3) & 1) * 8;
    const uint32_t aAddr = sbase + A_OFF + ((m0 + a_row) * A_STR + a_col) * 2;

    float acc[2][8][4];
#pragma unroll
    for (int mf = 0; mf < 2; mf++)
#pragma unroll
        for (int nf = 0; nf < 8; nf++)
#pragma unroll
            for (int q = 0; q < 4; q++) acc[mf][nf][q] = 0.f;

#pragma unroll 1
    for (int g = 0; g < TOTCH; g++) {
        const int c  = g & 3;
        const int nt = g >> 2;

        if (g + 1 < TOTCH) loadB(g + 1, (g + 1) & 1);

        const uint32_t bBase = sbase + B_OFF + (g & 1) * B_BUF;
#pragma unroll
        for (int ks = 0; ks < 4; ks++) {
            const int kkA = c * 64 + ks * 16;
            uint32_t ah[2][4], bh[8][2];
#pragma unroll
            for (int mf = 0; mf < 2; mf++)
                ldsm4(ah[mf][0], ah[mf][1], ah[mf][2], ah[mf][3],
                      aAddr + (mf * 16 * A_STR + kkA) * 2);
#pragma unroll
            for (int nf2 = 0; nf2 < 4; nf2++) {
                uint32_t ba = bBase +
                    ((n0 + nf2 * 16 + b_row) * B_STR + ks * 16 + b_col) * 2;
                ldsm4(bh[2 * nf2][0], bh[2 * nf2][1],
                      bh[2 * nf2 + 1][0], bh[2 * nf2 + 1][1], ba);
            }
#pragma unroll
            for (int mf = 0; mf < 2; mf++)
#pragma unroll
                for (int nf = 0; nf < 8; nf++)
                    MMA16816(acc[mf][nf], ah[mf], bh[nf]);
        }

        if (c == 3) {
            const int erow = lane >> 2;
            const int ecol = (lane & 3) * 2;
            const int bsel = (nt * 128 + n0) >> 8;
            __half* dst = (bsel == 0) ? g_q16 : (bsel == 1) ? g_k16 : g_v16;
#pragma unroll
            for (int mf = 0; mf < 2; mf++) {
                int R0 = bx * 128 + m0 + mf * 16 + erow;
                int w0 = R0 >> 6, t0 = R0 & 63;
                int R1 = R0 + 8;
                int w1 = R1 >> 6, t1 = R1 & 63;
#pragma unroll
                for (int nf = 0; nf < 8; nf++) {
                    int jg = nt * 128 + n0 + nf * 8 + ecol;
                    float bx0 = __ldg(&bias[jg]);
                    float bx1 = __ldg(&bias[jg + 1]);
                    int rem = jg & 255;
                    int h = rem >> 5, d = rem & 31;
                    int off0 = (((w0 << 3) + h) * WS2 + t0) * HD + d;
                    *(uint32_t*)&dst[off0] =
                        packh2(acc[mf][nf][0] + bx0, acc[mf][nf][1] + bx1);
                    int off1 = (((w1 << 3) + h) * WS2 + t1) * HD + d;
                    *(uint32_t*)&dst[off1] =
                        packh2(acc[mf][nf][2] + bx0, acc[mf][nf][3] + bx1);
                }
            }
#pragma unroll
            for (int mf = 0; mf < 2; mf++)
#pragma unroll
                for (int nf = 0; nf < 8; nf++)
#pragma unroll
                    for (int q = 0; q < 4; q++) acc[mf][nf][q] = 0.f;
        }

        CP_WAIT0();
        __syncthreads();
    }
}

// ---------------------------------------------------------------------------
// Fused attention + out-projection, 512 threads, grid 1024 (2 windows/CTA).
// SMEM phases:
//   P0/P1: K [0,81920) | V [81920,163840) | ps [163840,+7200) | rg [+512)
//   P2:    at (overlay K) [0,67584) | B bufs (overlay V) [81920,+2x20480)
// o is held PACKED in registers across the K->at overlay boundary.
// ---------------------------------------------------------------------------
#define QSTR  40
#define KV_SZ 81920                        // 16*64*40*2 bytes
#define KOFF  0
#define VOFF  KV_SZ
#define PSOFF (2 * KV_SZ)                  // 163840
#define RGOFF (PSOFF + 7200)               // 171040
#define FUSED_SMEM (RGOFF + 512)           // 171552
#define ATOFF 0
#define ATSTR 264                          // at: 128 x 264 halves = 67584 B
#define FB_OFF KV_SZ                       // overlays V
#define FB_BUF 20480                       // 256*40*2

__global__ __launch_bounds__(512, 1) void attn_proj(
    const float* __restrict__ pos_enc,
    const __half* __restrict__ wo16,
    const float* __restrict__ b_out,
    float* __restrict__ outp)
{
    extern __shared__ char smem[];
    const uint32_t sbase = smem_u32(smem);
    const int tid  = threadIdx.x;
    const int wid  = tid >> 5;
    const int lane = tid & 31;
    const int bx   = blockIdx.x;

    // ---- Phase 0: load K/V tiles, pos_enc, region ids ----
    {
#pragma unroll
        for (int tz = 0; tz < 2; tz++) {
            const __half* base = (tz == 0) ? g_k16 : g_v16;
            const uint32_t off = (tz == 0) ? KOFF : VOFF;
#pragma unroll
            for (int i = 0; i < 8; i++) {
                int idx = tid + i * 512;       // 4096 uint4
                int u = idx & 3, r = (idx >> 2) & 63, th = idx >> 8;
                uint4 v = *(const uint4*)(base +
                    ((bx * 16 + th) * 64 + r) * HD + u * 8);
                *(uint4*)(smem + off + ((th * 64 + r) * QSTR + u * 8) * 2) = v;
            }
        }
        float* psf = (float*)(smem + PSOFF);
        for (int i = tid; i < 1800; i += 512) psf[i] = pos_enc[i];
        int* rgp = (int*)(smem + RGOFF);
        if (tid < 128) {
            int win2 = tid >> 6, t = tid & 63;
            int widx = (bx * 2 + win2) & 63;
            int wy = widx >> 3, wx = widx & 7;
            int ry = (wy < 7) ? 0 : ((t >> 3) < 4 ? 1 : 2);
            int rx = (wx < 7) ? 0 : ((t & 7) < 4 ? 1 : 2);
            rgp[tid] = ry * 3 + rx;
        }
    }
    __syncthreads();

    // ---- Phase 1: attention; o kept packed in registers ----
    uint32_t opack[2][16];                 // [blk][mf*8 + nf*2 + r]
    const int win2 = wid >> 3;
    const int head = wid & 7;
    const int rowl = lane >> 2;
    const int colb = (lane & 3) * 2;
    {
        const int widx = (bx * 2 + win2) & 63;
        const bool use_mask = (widx >= 56) || ((widx & 7) == 7);
        const float* ps = (const float*)(smem + PSOFF) + head * 225;
        const int* rg = (const int*)(smem + RGOFF) + win2 * 64;
        const __half* qbase = g_q16 + (size_t)(bx * 16 + wid) * 64 * HD;
        const uint32_t kBase = sbase + KOFF + wid * 64 * QSTR * 2;
        const uint32_t vBase = sbase + VOFF + wid * 64 * QSTR * 2;

        const int b_row = (lane & 7) + ((lane >> 4) << 3);
        const int b_col = ((lane >> 3) & 1) * 8;
        const int v_row = (lane & 7) + ((lane >> 3) & 1) * 8;
        const int v_col = (lane >> 4) * 8;

#pragma unroll 1
        for (int blk = 0; blk < 2; blk++) {
            const int m0 = blk * 32;

            float s[2][8][4];
#pragma unroll
            for (int mf = 0; mf < 2; mf++)
#pragma unroll
                for (int nf = 0; nf < 8; nf++)
#pragma unroll
                    for (int q = 0; q < 4; q++) s[mf][nf][q] = 0.f;

#pragma unroll
            for (int ks = 0; ks < 2; ks++) {
                uint32_t ah[2][4], bh[8][2];
#pragma unroll
                for (int mf = 0; mf < 2; mf++) {
                    const __half* qr = qbase + (m0 + mf * 16 + rowl) * HD
                                             + ks * 16 + colb;
                    ah[mf][0] = *(const uint32_t*)qr;
                    ah[mf][1] = *(const uint32_t*)(qr + 8 * HD);
                    ah[mf][2] = *(const uint32_t*)(qr + 8);
                    ah[mf][3] = *(const uint32_t*)(qr + 8 * HD + 8);
                }
#pragma unroll
                for (int nf2 = 0; nf2 < 4; nf2++) {
                    uint32_t b = kBase +
                        ((nf2 * 16 + b_row) * QSTR + ks * 16 + b_col) * 2;
                    ldsm4(bh[2 * nf2][0], bh[2 * nf2][1],
                          bh[2 * nf2 + 1][0], bh[2 * nf2 + 1][1], b);
                }
#pragma unroll
                for (int mf = 0; mf < 2; mf++)
#pragma unroll
                    for (int nf = 0; nf < 8; nf++)
                        MMA16816(s[mf][nf], ah[mf], bh[nf]);
            }

#pragma unroll
            for (int mf = 0; mf < 2; mf++) {
                int t1a = m0 + mf * 16 + rowl, t1b = t1a + 8;
                int rca = ((t1a >> 3) + 7) * 15 + (t1a & 7) + 7;
                int rcb = ((t1b >> 3) + 7) * 15 + (t1b & 7) + 7;
                float mxa = -1e30f, mxb = -1e30f;
                if (use_mask) {
                    int rga = rg[t1a], rgb = rg[t1b];
#pragma unroll
                    for (int nf = 0; nf < 8; nf++)
#pragma unroll
                        for (int e = 0; e < 2; e++) {
                            int t2 = nf * 8 + colb + e;
                            int cc = (t2 >> 3) * 15 + (t2 & 7);
                            int rgc = rg[t2];
                            float va = fmaf(s[mf][nf][e], ATT_SCALE, ps[rca - cc]);
                            float vb = fmaf(s[mf][nf][2 + e], ATT_SCALE, ps[rcb - cc]);
                            if (rgc != rga) va = -1e30f;
                            if (rgc != rgb) vb = -1e30f;
                            s[mf][nf][e] = va;
                            s[mf][nf][2 + e] = vb;
                            mxa = fmaxf(mxa, va);
                            mxb = fmaxf(mxb, vb);
                        }
                } else {
#pragma unroll
                    for (int nf = 0; nf < 8; nf++)
#pragma unroll
                        for (int e = 0; e < 2; e++) {
                            int t2 = nf * 8 + colb + e;
                            int cc = (t2 >> 3) * 15 + (t2 & 7);
                            float va = fmaf(s[mf][nf][e], ATT_SCALE, ps[rca - cc]);
                            float vb = fmaf(s[mf][nf][2 + e], ATT_SCALE, ps[rcb - cc]);
                            s[mf][nf][e] = va;
                            s[mf][nf][2 + e] = vb;
                            mxa = fmaxf(mxa, va);
                            mxb = fmaxf(mxb, vb);
                        }
                }
                mxa = fmaxf(mxa, __shfl_xor_sync(0xffffffffu, mxa, 1));
                mxa = fmaxf(mxa, __shfl_xor_sync(0xffffffffu, mxa, 2));
                mxb = fmaxf(mxb, __shfl_xor_sync(0xffffffffu, mxb, 1));
                mxb = fmaxf(mxb, __shfl_xor_sync(0xffffffffu, mxb, 2));
                float sma = 0.f, smb = 0.f;
#pragma unroll
                for (int nf = 0; nf < 8; nf++)
#pragma unroll
                    for (int e = 0; e < 2; e++) {
                        float ea = __expf(s[mf][nf][e] - mxa);
                        float eb = __expf(s[mf][nf][2 + e] - mxb);
                        s[mf][nf][e] = ea;
                        s[mf][nf][2 + e] = eb;
                        sma += ea;
                        smb += eb;
                    }
                sma += __shfl_xor_sync(0xffffffffu, sma, 1);
                sma += __shfl_xor_sync(0xffffffffu, sma, 2);
                smb += __shfl_xor_sync(0xffffffffu, smb, 1);
                smb += __shfl_xor_sync(0xffffffffu, smb, 2);
                float ia = 1.0f / sma, ib = 1.0f / smb;
#pragma unroll
                for (int nf = 0; nf < 8; nf++) {
                    s[mf][nf][0] *= ia; s[mf][nf][1] *= ia;
                    s[mf][nf][2] *= ib; s[mf][nf][3] *= ib;
                }
            }

            float o[2][4][4];
#pragma unroll
            for (int mf = 0; mf < 2; mf++)
#pragma unroll
                for (int nf = 0; nf < 4; nf++)
#pragma unroll
                    for (int q = 0; q < 4; q++) o[mf][nf][q] = 0.f;

#pragma unroll
            for (int kf = 0; kf < 4; kf++) {
                uint32_t aP[2][4];
#pragma unroll
                for (int mf = 0; mf < 2; mf++) {
                    aP[mf][0] = packh2(s[mf][2 * kf][0],     s[mf][2 * kf][1]);
                    aP[mf][1] = packh2(s[mf][2 * kf][2],     s[mf][2 * kf][3]);
                    aP[mf][2] = packh2(s[mf][2 * kf + 1][0], s[mf][2 * kf + 1][1]);
                    aP[mf][3] = packh2(s[mf][2 * kf + 1][2], s[mf][2 * kf + 1][3]);
                }
                uint32_t bV[4][2];
#pragma unroll
                for (int dh = 0; dh < 2; dh++) {
                    uint32_t a = vBase +
                        ((kf * 16 + v_row) * QSTR + dh * 16 + v_col) * 2;
                    ldsm4t(bV[2 * dh][0], bV[2 * dh][1],
                           bV[2 * dh + 1][0], bV[2 * dh + 1][1], a);
                }
#pragma unroll
                for (int mf = 0; mf < 2; mf++)
#pragma unroll
                    for (int nf = 0; nf < 4; nf++)
                        MMA16816(o[mf][nf], aP[mf], bV[nf]);
            }

            // pack o into registers (no smem writes yet — K still live)
#pragma unroll
            for (int mf = 0; mf < 2; mf++)
#pragma unroll
                for (int nf = 0; nf < 4; nf++) {
                    opack[blk][mf * 8 + nf * 2 + 0] =
                        packh2(o[mf][nf][0], o[mf][nf][1]);
                    opack[blk][mf * 8 + nf * 2 + 1] =
                        packh2(o[mf][nf][2], o[mf][nf][3]);
                }
        }
    }
    __syncthreads();   // everyone done reading K/V

    // ---- spill packed o -> at tile (overlays K) ----
#pragma unroll
    for (int blk = 0; blk < 2; blk++)
#pragma unroll
        for (int mf = 0; mf < 2; mf++)
#pragma unroll
            for (int nf = 0; nf < 4; nf++) {
                int ra = win2 * 64 + blk * 32 + mf * 16 + rowl;
                int cc = head * 32 + nf * 8 + colb;
                *(uint32_t*)(smem + ATOFF + (ra * ATSTR + cc) * 2) =
                    opack[blk][mf * 8 + nf * 2 + 0];
                *(uint32_t*)(smem + ATOFF + ((ra + 8) * ATSTR + cc) * 2) =
                    opack[blk][mf * 8 + nf * 2 + 1];
            }
    __syncthreads();

    // ---- Phase 2: out-proj GEMM. A = at smem, B = wo16 (overlay V). ----
    {
        const int m0 = (wid & 3) * 32;
        const int n0 = (wid >> 2) * 64;

        auto loadB = [&](int gg, int b) {
            const int kk = gg * 32;
#pragma unroll
            for (int i = 0; i < 2; i++) {
                int idx = tid + i * 512;       // 1024 x 16B
                int r = idx >> 2, u = idx & 3;
                const __half* s = wo16 + r * DIM + kk + u * 8;
                uint32_t d = sbase + FB_OFF + b * FB_BUF + (r * QSTR + u * 8) * 2;
                CP_ASYNC16(d, s);
            }
            CP_COMMIT();
        };

        loadB(0, 0);
        CP_WAIT0();
        __syncthreads();

        const int a_row = lane & 15;
        const int a_col = (lane >> 4) * 8;
        const int b_row = (lane & 7) + ((lane >> 4) << 3);
        const int b_col = ((lane >> 3) & 1) * 8;
        const uint32_t aAddr = sbase + ATOFF + ((m0 + a_row) * ATSTR + a_col) * 2;

        float acc[2][8][4];
#pragma unroll
        for (int mf = 0; mf < 2; mf++)
#pragma unroll
            for (int nf = 0; nf < 8; nf++)
#pragma unroll
                for (int q = 0; q < 4; q++) acc[mf][nf][q] = 0.f;

#pragma unroll 1
        for (int g = 0; g < 8; g++) {
            if (g + 1 < 8) loadB(g + 1, (g + 1) & 1);

            const uint32_t bBase = sbase + FB_OFF + (g & 1) * FB_BUF;
#pragma unroll
            for (int ks = 0; ks < 2; ks++) {
                const int kkA = g * 32 + ks * 16;
                uint32_t ah[2][4], bh[8][2];
#pragma unroll
                for (int mf = 0; mf < 2; mf++)
                    ldsm4(ah[mf][0], ah[mf][1], ah[mf][2], ah[mf][3],
                          aAddr + (mf * 16 * ATSTR + kkA) * 2);
#pragma unroll
                for (int nf2 = 0; nf2 < 4; nf2++) {
                    uint32_t ba = bBase +
                        ((n0 + nf2 * 16 + b_row) * QSTR + ks * 16 + b_col) * 2;
                    ldsm4(bh[2 * nf2][0], bh[2 * nf2][1],
                          bh[2 * nf2 + 1][0], bh[2 * nf2 + 1][1], ba);
                }
#pragma unroll
                for (int mf = 0; mf < 2; mf++)
#pragma unroll
                    for (int nf = 0; nf < 8; nf++)
                        MMA16816(acc[mf][nf], ah[mf], bh[nf]);
            }
            CP_WAIT0();
            __syncthreads();
        }

        const int erow = lane >> 2;
        const int ecol = (lane & 3) * 2;
#pragma unroll
        for (int mf = 0; mf < 2; mf++) {
            int R0 = bx * 128 + m0 + mf * 16 + erow;
            int so0 = src_offset(R0);
            int so1 = src_offset(R0 + 8);
#pragma unroll
            for (int nf = 0; nf < 8; nf++) {
                int jg = n0 + nf * 8 + ecol;
                float bx0 = __ldg(&b_out[jg]);
                float bx1 = __ldg(&b_out[jg + 1]);
                *(float2*)&outp[so0 + jg] =
                    make_float2(acc[mf][nf][0] + bx0, acc[mf][nf][1] + bx1);
                *(float2*)&outp[so1 + jg] =
                    make_float2(acc[mf][nf][2] + bx0, acc[mf][nf][3] + bx1);
            }
        }
    }
}

// ---------------------------------------------------------------------------
extern "C" void kernel_launch(void* const* d_in, const int* in_sizes, int n_in,
                              void* d_out, int out_size)
{
    const float* x       = (const float*)d_in[0];
    const float* w_qkv   = (const float*)d_in[1];
    const float* b_qkv   = (const float*)d_in[2];
    const float* w_out   = (const float*)d_in[3];
    const float* b_out   = (const float*)d_in[4];
    const float* pos_enc = (const float*)d_in[5];
    float* out = (float*)d_out;

    cudaFuncSetAttribute(qkv_gemm, cudaFuncAttributeMaxDynamicSharedMemorySize, SMEM_SZ);
    cudaFuncSetAttribute(attn_proj, cudaFuncAttributeMaxDynamicSharedMemorySize, FUSED_SMEM);

    __half *wq16, *wo16;
    cudaGetSymbolAddress((void**)&wq16, g_wq16);
    cudaGetSymbolAddress((void**)&wo16, g_wo16);

    conv16_all<<<(NQ1 + NQ2) / 256, 256>>>(w_qkv, w_out);
    qkv_gemm<<<NTOK / 128, 256, SMEM_SZ>>>(x, wq16, b_qkv);
    attn_proj<<<NTOK / 128, 512, FUSED_SMEM>>>(pos_enc, wo16, b_out, out);
}